// round 2
// baseline (speedup 1.0000x reference)
#include <cuda_runtime.h>
#include <cuda_bf16.h>
#include <math.h>

// Problem constants
#define Bv 16
#define Sv 3136
#define Ev 768
#define Hv 16
#define Dv 48
#define NTOK (Bv * Sv)          // 50176
#define E3 (3 * Ev)             // 2304
#define CH 64                   // token chunk in middle kernel (3136 / 64 = 49)

// Scratch: device globals (no allocation allowed)
__device__ float g_qkv[(size_t)NTOK * E3];   // [token, 2304]
__device__ float g_mid[(size_t)NTOK * Ev];   // [token, 768] = b s (h d)

// ---------------------------------------------------------------------------
// SGEMM: C[M,N] = A[M,K] @ B[K,N] (+ bias[N]), all row-major fp32.
// 128x128 block tile, BK=8, 256 threads, 8x8 per thread. Requires
// M%128==0, N%128==0, K%8==0 (true for all our shapes).
// ---------------------------------------------------------------------------
__global__ __launch_bounds__(256) void sgemm128(
    const float* __restrict__ A, const float* __restrict__ B,
    float* __restrict__ C, const float* __restrict__ bias,
    int M, int N, int K)
{
    constexpr int BM = 128, BN = 128, BK = 8;
    __shared__ float As[BK][BM];   // transposed A tile
    __shared__ float Bs[BK][BN];

    const int tid  = threadIdx.x;
    const int cCol = blockIdx.x;   // N tile
    const int cRow = blockIdx.y;   // M tile

    // A tile load: 128x8 floats = 256 * float4. row=tid/2, col=(tid%2)*4
    const int aRow = tid >> 1;
    const int aCol = (tid & 1) * 4;
    // B tile load: 8x128 floats. row=tid/32, col=(tid%32)*4
    const int bRow = tid >> 5;
    const int bCol = (tid & 31) * 4;

    const int tr = (tid / 16) * 8;  // output sub-tile row
    const int tc = (tid % 16) * 8;  // output sub-tile col

    const float* Ab = A + (size_t)cRow * BM * K;
    const float* Bb = B + (size_t)cCol * BN;

    float acc[8][8];
    #pragma unroll
    for (int i = 0; i < 8; i++)
        #pragma unroll
        for (int j = 0; j < 8; j++) acc[i][j] = 0.f;

    for (int k0 = 0; k0 < K; k0 += BK) {
        float4 av = *(const float4*)(Ab + (size_t)aRow * K + k0 + aCol);
        As[aCol + 0][aRow] = av.x;
        As[aCol + 1][aRow] = av.y;
        As[aCol + 2][aRow] = av.z;
        As[aCol + 3][aRow] = av.w;
        *(float4*)&Bs[bRow][bCol] =
            *(const float4*)(Bb + (size_t)(k0 + bRow) * N + bCol);
        __syncthreads();

        #pragma unroll
        for (int kk = 0; kk < BK; kk++) {
            float4 a0 = *(const float4*)&As[kk][tr];
            float4 a1 = *(const float4*)&As[kk][tr + 4];
            float4 b0 = *(const float4*)&Bs[kk][tc];
            float4 b1 = *(const float4*)&Bs[kk][tc + 4];
            float ra[8] = {a0.x, a0.y, a0.z, a0.w, a1.x, a1.y, a1.z, a1.w};
            float rb[8] = {b0.x, b0.y, b0.z, b0.w, b1.x, b1.y, b1.z, b1.w};
            #pragma unroll
            for (int i = 0; i < 8; i++)
                #pragma unroll
                for (int j = 0; j < 8; j++)
                    acc[i][j] = fmaf(ra[i], rb[j], acc[i][j]);
        }
        __syncthreads();
    }

    float bv[8];
    #pragma unroll
    for (int j = 0; j < 8; j++)
        bv[j] = bias ? bias[(size_t)cCol * BN + tc + j] : 0.f;

    #pragma unroll
    for (int i = 0; i < 8; i++) {
        float* Cr = C + (size_t)(cRow * BM + tr + i) * N + (size_t)cCol * BN + tc;
        float4 o0, o1;
        o0.x = acc[i][0] + bv[0]; o0.y = acc[i][1] + bv[1];
        o0.z = acc[i][2] + bv[2]; o0.w = acc[i][3] + bv[3];
        o1.x = acc[i][4] + bv[4]; o1.y = acc[i][5] + bv[5];
        o1.z = acc[i][6] + bv[6]; o1.w = acc[i][7] + bv[7];
        *(float4*)(Cr + 0) = o0;
        *(float4*)(Cr + 4) = o1;
    }
}

// ---------------------------------------------------------------------------
// Middle kernel: one CTA per (b, h). Computes
//   G[i][j] = sum_s q[i,s] k[j,s];  nq[i] = ||q_i||;  nk[j] = ||k_j||
//   A = softmax_j( temp[h] * G[i][j] / (max(nq_i,eps) * max(nk_j,eps)) )
//   out[b, s, h*48 + i] = sum_j A[i][j] * v[j, s]
// q[i,s] = qkv[(b*S+s)*2304 + h*48 + i], k at +768, v at +1536.
// ---------------------------------------------------------------------------
__global__ __launch_bounds__(256) void xc_attn_mid(
    const float* __restrict__ qkv, const float* __restrict__ temp,
    float* __restrict__ out)
{
    __shared__ float qs[Dv][CH + 1];
    __shared__ float ks[Dv][CH + 1];
    __shared__ float Gs[Dv][Dv];
    __shared__ float nrm[2 * Dv];

    const int bh  = blockIdx.x;
    const int b   = bh / Hv;
    const int h   = bh % Hv;
    const int tid = threadIdx.x;
    const size_t base = ((size_t)b * Sv) * E3 + (size_t)h * Dv;

    float acc[9];
    #pragma unroll
    for (int p = 0; p < 9; p++) acc[p] = 0.f;
    float nacc = 0.f;

    // ---- Phase 1: gram matrix + squared norms over S in chunks ----
    for (int s0 = 0; s0 < Sv; s0 += CH) {
        for (int idx = tid; idx < Dv * CH; idx += 256) {
            int i  = idx % Dv;
            int sl = idx / Dv;
            size_t g = base + (size_t)(s0 + sl) * E3 + i;
            qs[i][sl] = qkv[g];
            ks[i][sl] = qkv[g + Ev];
        }
        __syncthreads();

        #pragma unroll
        for (int p = 0; p < 9; p++) {
            int pr = tid + p * 256;      // 0..2303
            int i = pr / Dv, j = pr % Dv;
            float a = 0.f;
            #pragma unroll 8
            for (int sl = 0; sl < CH; sl++)
                a = fmaf(qs[i][sl], ks[j][sl], a);
            acc[p] += a;
        }
        if (tid < 2 * Dv) {
            const float* row = (tid < Dv) ? qs[tid] : ks[tid - Dv];
            float a = 0.f;
            #pragma unroll 8
            for (int sl = 0; sl < CH; sl++)
                a = fmaf(row[sl], row[sl], a);
            nacc += a;
        }
        __syncthreads();
    }

    #pragma unroll
    for (int p = 0; p < 9; p++) {
        int pr = tid + p * 256;
        Gs[pr / Dv][pr % Dv] = acc[p];
    }
    if (tid < 2 * Dv) nrm[tid] = fmaxf(sqrtf(nacc), 1e-12f);
    __syncthreads();

    // ---- Phase 2: scaled softmax per row (warp w handles rows w, w+8, ...) ----
    const float T = temp[h];
    const int warp = tid >> 5, lane = tid & 31;
    for (int i = warp; i < Dv; i += 8) {
        float inq = T / nrm[i];
        int j0 = lane, j1 = lane + 32;
        float v0 = Gs[i][j0] * inq / nrm[Dv + j0];
        float v1 = (j1 < Dv) ? Gs[i][j1] * inq / nrm[Dv + j1] : -INFINITY;
        float m = fmaxf(v0, v1);
        #pragma unroll
        for (int o = 16; o; o >>= 1) m = fmaxf(m, __shfl_xor_sync(~0u, m, o));
        float e0 = expf(v0 - m);
        float e1 = (j1 < Dv) ? expf(v1 - m) : 0.f;
        float ssum = e0 + e1;
        #pragma unroll
        for (int o = 16; o; o >>= 1) ssum += __shfl_xor_sync(~0u, ssum, o);
        float inv = 1.f / ssum;
        Gs[i][j0] = e0 * inv;
        if (j1 < Dv) Gs[i][j1] = e1 * inv;
    }
    __syncthreads();

    // ---- Phase 3: out = A @ v, streamed over S (reuse qs as v tile) ----
    const size_t vbase = base + 2 * Ev;
    const size_t obase = ((size_t)b * Sv) * Ev + (size_t)h * Dv;
    for (int s0 = 0; s0 < Sv; s0 += CH) {
        for (int idx = tid; idx < Dv * CH; idx += 256) {
            int j  = idx % Dv;
            int sl = idx / Dv;
            qs[j][sl] = qkv[vbase + (size_t)(s0 + sl) * E3 + j];
        }
        __syncthreads();
        for (int idx = tid; idx < Dv * CH; idx += 256) {
            int i  = idx % Dv;
            int sl = idx / Dv;
            float a = 0.f;
            #pragma unroll
            for (int j = 0; j < Dv; j++)
                a = fmaf(Gs[i][j], qs[j][sl], a);
            out[obase + (size_t)(s0 + sl) * Ev + i] = a;
        }
        __syncthreads();
    }
}

// ---------------------------------------------------------------------------
// Launch
// ---------------------------------------------------------------------------
extern "C" void kernel_launch(void* const* d_in, const int* in_sizes, int n_in,
                              void* d_out, int out_size)
{
    const float* x      = (const float*)d_in[0];  // [16,3136,768]
    const float* W_qkv  = (const float*)d_in[1];  // [768,2304]
    const float* W_proj = (const float*)d_in[2];  // [768,768]
    const float* b_proj = (const float*)d_in[3];  // [768]
    const float* temp   = (const float*)d_in[4];  // [16,1,1]
    float* outp = (float*)d_out;

    float* qkv = nullptr;
    float* mid = nullptr;
    cudaGetSymbolAddress((void**)&qkv, g_qkv);
    cudaGetSymbolAddress((void**)&mid, g_mid);

    // GEMM1: [50176, 768] @ [768, 2304]
    {
        dim3 grid(E3 / 128, NTOK / 128);
        sgemm128<<<grid, 256>>>(x, W_qkv, qkv, nullptr, NTOK, E3, Ev);
    }
    // Middle: 256 CTAs (one per b,h)
    xc_attn_mid<<<Bv * Hv, 256>>>(qkv, temp, mid);
    // GEMM2: [50176, 768] @ [768, 768] + bias
    {
        dim3 grid(Ev / 128, NTOK / 128);
        sgemm128<<<grid, 256>>>(mid, W_proj, outp, b_proj, NTOK, Ev, Ev);
    }
}

// round 4
// speedup vs baseline: 1.4770x; 1.4770x over previous
#include <cuda_runtime.h>
#include <cuda_bf16.h>
#include <math.h>
#include <stdint.h>

// ---------------- problem constants ----------------
#define Bv 16
#define Sv 3136
#define Ev 768
#define Hv 16
#define Dv 48
#define NTOK (Bv * Sv)      // 50176
#define KPP 2304            // tripled K in bf16 elems (3 * 768)
#define LDK 4608            // bytes per packed row (KPP * 2)
#define LDKU 1152           // u32 per packed row
#define NKCH 36             // K chunks of 64 bf16 (128 bytes)
#define NSTG 3
#define STG_BYTES 32768     // 16KB A + 16KB B per stage
#define GEMM_SMEM (NSTG * STG_BYTES)   // 98304

// ---------------- scratch (device globals; no allocation allowed) ----------
__device__ uint32_t g_x2[(size_t)NTOK * LDKU];     // packed bf16 triplets of x
__device__ float    g_qkv[(size_t)NTOK * 2304];    // fp32 qkv = x @ W_qkv
__device__ uint32_t g_mid2[(size_t)NTOK * LDKU];   // packed bf16 triplets of mid
__device__ uint32_t g_wt1[(size_t)2304 * LDKU];    // W_qkv^T packed (B layout)
__device__ uint32_t g_wt2[(size_t)768 * LDKU];     // W_proj^T packed
__device__ float    g_gram[256 * 2304];            // per (b,h) 48x48 gram / attn
__device__ float    g_nrm[256 * 96];               // per (b,h) squared norms

// ---------------- helpers ----------------
__device__ __forceinline__ uint32_t s2u(const void* p) {
    uint32_t a;
    asm("{ .reg .u64 t; cvta.to.shared.u64 t, %1; cvt.u32.u64 %0, t; }"
        : "=r"(a) : "l"(p));
    return a;
}
#define SWZ(o) ((o) ^ (((o) >> 3) & 0x70))

__device__ __forceinline__ void cpasync16(uint32_t s, const void* g) {
    asm volatile("cp.async.cg.shared.global [%0], [%1], 16;\n" :: "r"(s), "l"(g));
}
__device__ __forceinline__ void cp_commit() {
    asm volatile("cp.async.commit_group;\n");
}
template <int N> __device__ __forceinline__ void cp_wait() {
    asm volatile("cp.async.wait_group %0;\n" :: "n"(N));
}
__device__ __forceinline__ void ldm4(uint32_t& r0, uint32_t& r1, uint32_t& r2,
                                     uint32_t& r3, uint32_t a) {
    asm volatile("ldmatrix.sync.aligned.m8n8.x4.shared.b16 {%0,%1,%2,%3}, [%4];"
                 : "=r"(r0), "=r"(r1), "=r"(r2), "=r"(r3) : "r"(a));
}
__device__ __forceinline__ void mma16816(float* d, const uint32_t* a,
                                         const uint32_t* b) {
    asm volatile(
        "mma.sync.aligned.m16n8k16.row.col.f32.bf16.bf16.f32 "
        "{%0,%1,%2,%3}, {%4,%5,%6,%7}, {%8,%9}, {%0,%1,%2,%3};"
        : "+f"(d[0]), "+f"(d[1]), "+f"(d[2]), "+f"(d[3])
        : "r"(a[0]), "r"(a[1]), "r"(a[2]), "r"(a[3]), "r"(b[0]), "r"(b[1]));
}
__device__ __forceinline__ void split2(float x, uint32_t& h, uint32_t& l) {
    __nv_bfloat16 hb = __float2bfloat16(x);
    float rem = x - __bfloat162float(hb);
    __nv_bfloat16 lb = __float2bfloat16(rem);
    h = (uint32_t)__bfloat16_as_ushort(hb);
    l = (uint32_t)__bfloat16_as_ushort(lb);
}

// ---------------------------------------------------------------------------
// bf16 mma.sync GEMM: C[M,N] (fp32) = A'' @ B''^T over packed triplet K.
// A: [rows, KPP] bf16 row-major packed; B: [N, KPP] bf16 row-major packed.
// CTA tile 128x128, BK=64, 8 warps of 32x64, 3-stage cp.async pipeline.
// ---------------------------------------------------------------------------
__global__ __launch_bounds__(256, 2) void gemm_mma(
    const char* __restrict__ A, const char* __restrict__ B,
    float* __restrict__ C, const float* __restrict__ bias, int N, int NT)
{
    extern __shared__ char sm[];
    const int tid  = threadIdx.x;
    const int wid  = tid >> 5, lane = tid & 31;
    const int wm   = wid & 3;          // warp m index (0-3), 32 rows each
    const int wn   = wid >> 2;         // warp n index (0-1), 64 cols each
    const int bm   = blockIdx.x / NT, bn = blockIdx.x % NT;
    const uint32_t smb = s2u(sm);

    const char* Ab = A + (size_t)bm * 128 * LDK;
    const char* Bb = B + (size_t)bn * 128 * LDK;

    // per-thread cp.async source/dest (A: 128 rows x 128B, B: same)
    const int ldr = tid >> 1;              // 0..127 row
    const int ldc = (tid & 1) * 64;        // byte col 0 or 64

    auto loadch = [&](int sp, int ck) {
        uint32_t sa = smb + sp * STG_BYTES;
        uint32_t sb = sa + 16384;
        const char* a0 = Ab + ck * 128;
        const char* b0 = Bb + ck * 128;
        #pragma unroll
        for (int i = 0; i < 4; i++) {
            int cb = ldc + i * 16;
            cpasync16(sa + SWZ(ldr * 128 + cb), a0 + (size_t)ldr * LDK + cb);
            cpasync16(sb + SWZ(ldr * 128 + cb), b0 + (size_t)ldr * LDK + cb);
        }
        cp_commit();
    };

    float acc[2][8][4];
    #pragma unroll
    for (int m = 0; m < 2; m++)
        #pragma unroll
        for (int n = 0; n < 8; n++)
            #pragma unroll
            for (int p = 0; p < 4; p++) acc[m][n][p] = 0.f;

    loadch(0, 0);
    loadch(1, 1);

    // per-lane ldmatrix address pieces
    const int a_row = (lane & 7) + ((lane >> 3) & 1) * 8;   // within 16-row blk
    const int a_cb  = (lane >> 4) * 16;
    const int b_row = (lane & 7) + (lane >> 4) * 8;
    const int b_cb  = ((lane >> 3) & 1) * 16;

    for (int k = 0; k < NKCH; k++) {
        int kp = k + 2;
        if (kp < NKCH) loadch(kp % NSTG, kp);
        else cp_commit();
        cp_wait<2>();
        __syncthreads();

        uint32_t sa = smb + (k % NSTG) * STG_BYTES;
        uint32_t sb = sa + 16384;
        #pragma unroll
        for (int ks = 0; ks < 4; ks++) {
            uint32_t af[2][4], bf[8][2];
            #pragma unroll
            for (int mb = 0; mb < 2; mb++) {
                int r = wm * 32 + mb * 16 + a_row;
                ldm4(af[mb][0], af[mb][1], af[mb][2], af[mb][3],
                     sa + SWZ(r * 128 + ks * 32 + a_cb));
            }
            #pragma unroll
            for (int nb2 = 0; nb2 < 4; nb2++) {
                int r = wn * 64 + nb2 * 16 + b_row;
                ldm4(bf[2 * nb2][0], bf[2 * nb2][1],
                     bf[2 * nb2 + 1][0], bf[2 * nb2 + 1][1],
                     sb + SWZ(r * 128 + ks * 32 + b_cb));
            }
            #pragma unroll
            for (int mb = 0; mb < 2; mb++)
                #pragma unroll
                for (int nb = 0; nb < 8; nb++)
                    mma16816(acc[mb][nb], af[mb], bf[nb]);
        }
        __syncthreads();
    }

    // Epilogue: direct register -> global (float2 per mma half)
    float* Cb = C + (size_t)(bm * 128 + wm * 32) * N + (size_t)bn * 128 + wn * 64;
    const int er = lane >> 2;            // 0..7
    const int ec = (lane & 3) * 2;       // 0,2,4,6
    #pragma unroll
    for (int mb = 0; mb < 2; mb++) {
        #pragma unroll
        for (int nb = 0; nb < 8; nb++) {
            int col = nb * 8 + ec;
            float bx = 0.f, by = 0.f;
            if (bias) {
                const float* bp = bias + (size_t)bn * 128 + wn * 64 + col;
                bx = bp[0]; by = bp[1];
            }
            float2 v0 = {acc[mb][nb][0] + bx, acc[mb][nb][1] + by};
            float2 v1 = {acc[mb][nb][2] + bx, acc[mb][nb][3] + by};
            *(float2*)(Cb + (size_t)(mb * 16 + er) * N + col) = v0;
            *(float2*)(Cb + (size_t)(mb * 16 + er + 8) * N + col) = v1;
        }
    }
}

// ---------------------------------------------------------------------------
// Conversion kernels (fp32 -> bf16 hi/lo triplets, packed 2 elems -> 3 u32)
// A layout per k: [hi, hi, lo]; B layout per k: [hi, lo, hi]
// ---------------------------------------------------------------------------
__global__ void pack_act(const float* __restrict__ in, uint32_t* __restrict__ out,
                         int npairs)
{
    int t = blockIdx.x * 256 + threadIdx.x;
    if (t >= npairs) return;
    float2 xv = ((const float2*)in)[t];
    uint32_t h0, l0, h1, l1;
    split2(xv.x, h0, l0);
    split2(xv.y, h1, l1);
    out[3 * (size_t)t + 0] = h0 | (h0 << 16);
    out[3 * (size_t)t + 1] = l0 | (h1 << 16);
    out[3 * (size_t)t + 2] = h1 | (l1 << 16);
}

__global__ void pack_wt(const float* __restrict__ W, uint32_t* __restrict__ out, int N)
{   // W: [768, N] row-major; out: [N, 1152] u32 (transposed, B-triplet layout)
    int t = blockIdx.x * 256 + threadIdx.x;
    if (t >= N * 384) return;
    int n = t / 384, kp = t % 384;
    float x0 = W[(size_t)(2 * kp) * N + n];
    float x1 = W[(size_t)(2 * kp + 1) * N + n];
    uint32_t h0, l0, h1, l1;
    split2(x0, h0, l0);
    split2(x1, h1, l1);
    uint32_t* o = out + (size_t)n * LDKU + 3 * kp;
    o[0] = h0 | (l0 << 16);
    o[1] = h0 | (h1 << 16);
    o[2] = l1 | (h1 << 16);
}

__global__ void zero2(float* a, int na, float* b, int nb)
{
    int t = blockIdx.x * 256 + threadIdx.x;
    if (t < na) a[t] = 0.f;
    if (t < nb) b[t] = 0.f;
}

// ---------------------------------------------------------------------------
// Middle stage: gram+norm (split over S), softmax, apply (writes packed bf16)
// ---------------------------------------------------------------------------
#define GCH 56
__global__ __launch_bounds__(256) void k_gram(
    const float* __restrict__ qkv, float* __restrict__ gram, float* __restrict__ nrm)
{
    __shared__ float qs[Dv][GCH + 1];
    __shared__ float ks[Dv][GCH + 1];
    const int bh = blockIdx.x >> 3, ck = blockIdx.x & 7;
    const int b = bh >> 4, h = bh & 15;
    const int tid = threadIdx.x;
    const size_t base = ((size_t)b * Sv + ck * 392) * 2304 + (size_t)h * Dv;

    float acc[9];
    #pragma unroll
    for (int p = 0; p < 9; p++) acc[p] = 0.f;
    float na = 0.f;

    for (int s0 = 0; s0 < 392; s0 += GCH) {
        for (int idx = tid; idx < Dv * GCH; idx += 256) {
            int i = idx % Dv, sl = idx / Dv;
            size_t g = base + (size_t)(s0 + sl) * 2304 + i;
            qs[i][sl] = qkv[g];
            ks[i][sl] = qkv[g + Ev];
        }
        __syncthreads();
        #pragma unroll
        for (int p = 0; p < 9; p++) {
            int pr = tid + p * 256;
            int i = pr / Dv, j = pr % Dv;
            float a = 0.f;
            #pragma unroll 8
            for (int sl = 0; sl < GCH; sl++) a = fmaf(qs[i][sl], ks[j][sl], a);
            acc[p] += a;
        }
        if (tid < 2 * Dv) {
            const float* row = (tid < Dv) ? qs[tid] : ks[tid - Dv];
            float a = 0.f;
            #pragma unroll 8
            for (int sl = 0; sl < GCH; sl++) a = fmaf(row[sl], row[sl], a);
            na += a;
        }
        __syncthreads();
    }
    #pragma unroll
    for (int p = 0; p < 9; p++)
        atomicAdd(gram + (size_t)bh * 2304 + tid + p * 256, acc[p]);
    if (tid < 96) atomicAdd(nrm + (size_t)bh * 96 + tid, na);
}

__global__ __launch_bounds__(256) void k_soft(
    float* __restrict__ gram, const float* __restrict__ nrm2,
    const float* __restrict__ temp)
{
    __shared__ float Gs[Dv][Dv];
    __shared__ float nr[96];
    const int bh = blockIdx.x;
    const int h = bh & 15;
    const int tid = threadIdx.x;
    for (int idx = tid; idx < 2304; idx += 256)
        Gs[idx / Dv][idx % Dv] = gram[(size_t)bh * 2304 + idx];
    if (tid < 96) nr[tid] = fmaxf(sqrtf(nrm2[(size_t)bh * 96 + tid]), 1e-12f);
    __syncthreads();
    const float T = temp[h];
    const int warp = tid >> 5, lane = tid & 31;
    for (int i = warp; i < Dv; i += 8) {
        float inq = T / nr[i];
        int j0 = lane, j1 = lane + 32;
        float v0 = Gs[i][j0] * inq / nr[Dv + j0];
        float v1 = (j1 < Dv) ? Gs[i][j1] * inq / nr[Dv + j1] : -INFINITY;
        float m = fmaxf(v0, v1);
        #pragma unroll
        for (int o = 16; o; o >>= 1) m = fmaxf(m, __shfl_xor_sync(~0u, m, o));
        float e0 = expf(v0 - m);
        float e1 = (j1 < Dv) ? expf(v1 - m) : 0.f;
        float ss = e0 + e1;
        #pragma unroll
        for (int o = 16; o; o >>= 1) ss += __shfl_xor_sync(~0u, ss, o);
        float inv = 1.f / ss;
        gram[(size_t)bh * 2304 + i * Dv + j0] = e0 * inv;
        if (j1 < Dv) gram[(size_t)bh * 2304 + i * Dv + j1] = e1 * inv;
    }
}

#define ACH 64
__global__ __launch_bounds__(256) void k_apply(
    const float* __restrict__ qkv, const float* __restrict__ attn,
    uint32_t* __restrict__ out)
{
    __shared__ float As_[Dv][Dv];
    __shared__ float vs[Dv][ACH + 1];
    const int bh = blockIdx.x / 49, ck = blockIdx.x % 49;
    const int b = bh >> 4, h = bh & 15;
    const int tid = threadIdx.x;
    for (int idx = tid; idx < 2304; idx += 256)
        As_[idx / Dv][idx % Dv] = attn[(size_t)bh * 2304 + idx];
    const size_t vbase = ((size_t)b * Sv + ck * ACH) * 2304 + 2 * Ev + (size_t)h * Dv;
    for (int idx = tid; idx < Dv * ACH; idx += 256) {
        int j = idx % Dv, sl = idx / Dv;
        vs[j][sl] = qkv[vbase + (size_t)sl * 2304 + j];
    }
    __syncthreads();
    const size_t obase = ((size_t)b * Sv + ck * ACH) * LDKU;
    for (int idx = tid; idx < 24 * ACH; idx += 256) {
        int i2 = idx % 24, sl = idx / 24;
        int i0 = 2 * i2;
        float a0 = 0.f, a1 = 0.f;
        #pragma unroll
        for (int j = 0; j < Dv; j++) {
            float v = vs[j][sl];
            a0 = fmaf(As_[i0][j], v, a0);
            a1 = fmaf(As_[i0 + 1][j], v, a1);
        }
        uint32_t h0, l0, h1, l1;
        split2(a0, h0, l0);
        split2(a1, h1, l1);
        uint32_t* o = out + obase + (size_t)sl * LDKU + 3 * (h * 24 + i2);
        o[0] = h0 | (h0 << 16);
        o[1] = l0 | (h1 << 16);
        o[2] = h1 | (l1 << 16);
    }
}

// ---------------------------------------------------------------------------
// Launch
// ---------------------------------------------------------------------------
extern "C" void kernel_launch(void* const* d_in, const int* in_sizes, int n_in,
                              void* d_out, int out_size)
{
    const float* x      = (const float*)d_in[0];
    const float* W_qkv  = (const float*)d_in[1];
    const float* W_proj = (const float*)d_in[2];
    const float* b_proj = (const float*)d_in[3];
    const float* temp   = (const float*)d_in[4];
    float* outp = (float*)d_out;

    uint32_t *x2, *mid2, *wt1, *wt2;
    float *qkv, *gram, *nrm;
    cudaGetSymbolAddress((void**)&x2, g_x2);
    cudaGetSymbolAddress((void**)&mid2, g_mid2);
    cudaGetSymbolAddress((void**)&wt1, g_wt1);
    cudaGetSymbolAddress((void**)&wt2, g_wt2);
    cudaGetSymbolAddress((void**)&qkv, g_qkv);
    cudaGetSymbolAddress((void**)&gram, g_gram);
    cudaGetSymbolAddress((void**)&nrm, g_nrm);

    cudaFuncSetAttribute(gemm_mma, cudaFuncAttributeMaxDynamicSharedMemorySize,
                         GEMM_SMEM);

    // 1. pack activations x -> bf16 triplets
    int npairs = NTOK * 384;
    pack_act<<<npairs / 256, 256>>>(x, x2, npairs);
    // 2. pack weights (transposed, B layout)
    pack_wt<<<(2304 * 384) / 256, 256>>>(W_qkv, wt1, 2304);
    pack_wt<<<(768 * 384) / 256, 256>>>(W_proj, wt2, 768);
    // 3. GEMM1: qkv = x @ W_qkv   [50176 x 2304]
    gemm_mma<<<392 * 18, 256, GEMM_SMEM>>>((const char*)x2, (const char*)wt1,
                                           qkv, nullptr, 2304, 18);
    // 4. middle
    zero2<<<(256 * 2304 + 255) / 256, 256>>>(gram, 256 * 2304, nrm, 256 * 96);
    k_gram<<<256 * 8, 256>>>(qkv, gram, nrm);
    k_soft<<<256, 256>>>(gram, nrm, temp);
    k_apply<<<256 * 49, 256>>>(qkv, gram, mid2);
    // 5. GEMM2: out = mid @ W_proj + b_proj   [50176 x 768]
    gemm_mma<<<392 * 6, 256, GEMM_SMEM>>>((const char*)mid2, (const char*)wt2,
                                          outp, b_proj, 768, 6);
}

// round 5
// speedup vs baseline: 1.5085x; 1.0213x over previous
#include <cuda_runtime.h>
#include <cuda_bf16.h>
#include <math.h>
#include <stdint.h>

// ---------------- problem constants ----------------
#define Bv 16
#define Sv 3136
#define Ev 768
#define Hv 16
#define Dv 48
#define NTOK (Bv * Sv)      // 50176
#define KPP 2304            // tripled K in bf16 elems (3 * 768)
#define LDK 4608            // bytes per packed row (KPP * 2)
#define LDKU 1152           // u32 per packed row
#define NKCH 36             // K chunks of 64 bf16 (128 bytes)
#define NSTG 3
#define STG_BYTES 32768     // 16KB A + 16KB B per stage
#define GEMM_SMEM (NSTG * STG_BYTES)   // 98304

// ---------------- scratch (device globals; no allocation allowed) ----------
__device__ uint32_t g_x2[(size_t)NTOK * LDKU];     // packed bf16 triplets of x
__device__ float    g_qkv[(size_t)NTOK * 2304];    // fp32 qkv = x @ W_qkv
__device__ uint32_t g_mid2[(size_t)NTOK * LDKU];   // packed bf16 triplets of mid
__device__ uint32_t g_wt1[(size_t)2304 * LDKU];    // W_qkv^T packed (B layout)
__device__ uint32_t g_wt2[(size_t)768 * LDKU];     // W_proj^T packed
__device__ float    g_gram[256 * 2304];            // per (b,h) 48x48 gram / attn
__device__ float    g_nrm[256 * 96];               // per (b,h) squared norms

// ---------------- helpers ----------------
__device__ __forceinline__ uint32_t s2u(const void* p) {
    uint32_t a;
    asm("{ .reg .u64 t; cvta.to.shared.u64 t, %1; cvt.u32.u64 %0, t; }"
        : "=r"(a) : "l"(p));
    return a;
}
#define SWZ(o) ((o) ^ (((o) >> 3) & 0x70))

__device__ __forceinline__ void cpasync16(uint32_t s, const void* g) {
    asm volatile("cp.async.cg.shared.global [%0], [%1], 16;\n" :: "r"(s), "l"(g));
}
__device__ __forceinline__ void cp_commit() {
    asm volatile("cp.async.commit_group;\n");
}
template <int N> __device__ __forceinline__ void cp_wait() {
    asm volatile("cp.async.wait_group %0;\n" :: "n"(N));
}
__device__ __forceinline__ void ldm4(uint32_t& r0, uint32_t& r1, uint32_t& r2,
                                     uint32_t& r3, uint32_t a) {
    asm volatile("ldmatrix.sync.aligned.m8n8.x4.shared.b16 {%0,%1,%2,%3}, [%4];"
                 : "=r"(r0), "=r"(r1), "=r"(r2), "=r"(r3) : "r"(a));
}
__device__ __forceinline__ void mma16816(float* d, const uint32_t* a,
                                         const uint32_t* b) {
    asm volatile(
        "mma.sync.aligned.m16n8k16.row.col.f32.bf16.bf16.f32 "
        "{%0,%1,%2,%3}, {%4,%5,%6,%7}, {%8,%9}, {%0,%1,%2,%3};"
        : "+f"(d[0]), "+f"(d[1]), "+f"(d[2]), "+f"(d[3])
        : "r"(a[0]), "r"(a[1]), "r"(a[2]), "r"(a[3]), "r"(b[0]), "r"(b[1]));
}
__device__ __forceinline__ void split2(float x, uint32_t& h, uint32_t& l) {
    __nv_bfloat16 hb = __float2bfloat16(x);
    float rem = x - __bfloat162float(hb);
    __nv_bfloat16 lb = __float2bfloat16(rem);
    h = (uint32_t)__bfloat16_as_ushort(hb);
    l = (uint32_t)__bfloat16_as_ushort(lb);
}

// ---------------------------------------------------------------------------
// bf16 mma.sync GEMM: C[M,N] (fp32) = A'' @ B''^T over packed triplet K.
// CTA tile 128x128, BK=64 bf16, 8 warps of 32x64, 3-stage cp.async pipeline.
// One __syncthreads per chunk; ldmatrix fragments double-buffered across the
// four ks sub-steps to hide LDSM latency under the MMA burst.
// ---------------------------------------------------------------------------
__global__ __launch_bounds__(256, 2) void gemm_mma(
    const char* __restrict__ A, const char* __restrict__ B,
    float* __restrict__ C, const float* __restrict__ bias, int N, int NT)
{
    extern __shared__ char sm[];
    const int tid  = threadIdx.x;
    const int wid  = tid >> 5, lane = tid & 31;
    const int wm   = wid & 3;          // warp m index (0-3), 32 rows each
    const int wn   = wid >> 2;         // warp n index (0-1), 64 cols each
    const int bm   = blockIdx.x / NT, bn = blockIdx.x % NT;
    const uint32_t smb = s2u(sm);

    const char* Ab = A + (size_t)bm * 128 * LDK;
    const char* Bb = B + (size_t)bn * 128 * LDK;

    const int ldr = tid >> 1;              // 0..127 row
    const int ldc = (tid & 1) * 64;        // byte col 0 or 64

    auto loadch = [&](int sp, int ck) {
        uint32_t sa = smb + sp * STG_BYTES;
        uint32_t sb = sa + 16384;
        const char* a0 = Ab + ck * 128;
        const char* b0 = Bb + ck * 128;
        #pragma unroll
        for (int i = 0; i < 4; i++) {
            int cb = ldc + i * 16;
            cpasync16(sa + SWZ(ldr * 128 + cb), a0 + (size_t)ldr * LDK + cb);
            cpasync16(sb + SWZ(ldr * 128 + cb), b0 + (size_t)ldr * LDK + cb);
        }
        cp_commit();
    };

    float acc[2][8][4];
    #pragma unroll
    for (int m = 0; m < 2; m++)
        #pragma unroll
        for (int n = 0; n < 8; n++)
            #pragma unroll
            for (int p = 0; p < 4; p++) acc[m][n][p] = 0.f;

    loadch(0, 0);
    loadch(1, 1);

    // per-lane ldmatrix address pieces
    const int a_row = (lane & 7) + ((lane >> 3) & 1) * 8;
    const int a_cb  = (lane >> 4) * 16;
    const int b_row = (lane & 7) + (lane >> 4) * 8;
    const int b_cb  = ((lane >> 3) & 1) * 16;

    uint32_t af[2][2][4], bf[2][8][2];

    auto ldfrag = [&](uint32_t sa, uint32_t sb, int ks, int buf) {
        #pragma unroll
        for (int mb = 0; mb < 2; mb++) {
            int r = wm * 32 + mb * 16 + a_row;
            ldm4(af[buf][mb][0], af[buf][mb][1], af[buf][mb][2], af[buf][mb][3],
                 sa + SWZ(r * 128 + ks * 32 + a_cb));
        }
        #pragma unroll
        for (int nb2 = 0; nb2 < 4; nb2++) {
            int r = wn * 64 + nb2 * 16 + b_row;
            ldm4(bf[buf][2 * nb2][0], bf[buf][2 * nb2][1],
                 bf[buf][2 * nb2 + 1][0], bf[buf][2 * nb2 + 1][1],
                 sb + SWZ(r * 128 + ks * 32 + b_cb));
        }
    };

    for (int k = 0; k < NKCH; k++) {
        cp_wait<1>();          // group k complete (k+1 may still be in flight)
        __syncthreads();       // publishes stage k%3; proves stage (k-1)%3 free

        int kp = k + 2;
        if (kp < NKCH) loadch(kp % NSTG, kp);   // overwrites stage (k-1)%3
        else cp_commit();                        // keep group count uniform

        uint32_t sa = smb + (k % NSTG) * STG_BYTES;
        uint32_t sb = sa + 16384;

        ldfrag(sa, sb, 0, 0);
        #pragma unroll
        for (int ks = 0; ks < 4; ks++) {
            int c = ks & 1;
            if (ks < 3) ldfrag(sa, sb, ks + 1, c ^ 1);
            #pragma unroll
            for (int mb = 0; mb < 2; mb++)
                #pragma unroll
                for (int nb = 0; nb < 8; nb++)
                    mma16816(acc[mb][nb], af[c][mb], bf[c][nb]);
        }
    }

    // Epilogue: direct register -> global
    float* Cb = C + (size_t)(bm * 128 + wm * 32) * N + (size_t)bn * 128 + wn * 64;
    const int er = lane >> 2;
    const int ec = (lane & 3) * 2;
    float bvs[8][2];
    #pragma unroll
    for (int nb = 0; nb < 8; nb++) {
        if (bias) {
            const float* bp = bias + (size_t)bn * 128 + wn * 64 + nb * 8 + ec;
            bvs[nb][0] = bp[0]; bvs[nb][1] = bp[1];
        } else { bvs[nb][0] = 0.f; bvs[nb][1] = 0.f; }
    }
    #pragma unroll
    for (int mb = 0; mb < 2; mb++) {
        #pragma unroll
        for (int nb = 0; nb < 8; nb++) {
            int col = nb * 8 + ec;
            float2 v0 = {acc[mb][nb][0] + bvs[nb][0], acc[mb][nb][1] + bvs[nb][1]};
            float2 v1 = {acc[mb][nb][2] + bvs[nb][0], acc[mb][nb][3] + bvs[nb][1]};
            *(float2*)(Cb + (size_t)(mb * 16 + er) * N + col) = v0;
            *(float2*)(Cb + (size_t)(mb * 16 + er + 8) * N + col) = v1;
        }
    }
}

// ---------------------------------------------------------------------------
// Conversion kernels (fp32 -> bf16 hi/lo triplets)
// A layout per k: [hi, hi, lo]; B layout per k: [hi, lo, hi]
// ---------------------------------------------------------------------------
__global__ void pack_act(const float* __restrict__ in, uint32_t* __restrict__ out,
                         int npairs)
{
    int t = blockIdx.x * 256 + threadIdx.x;
    if (t >= npairs) return;
    float2 xv = ((const float2*)in)[t];
    uint32_t h0, l0, h1, l1;
    split2(xv.x, h0, l0);
    split2(xv.y, h1, l1);
    out[3 * (size_t)t + 0] = h0 | (h0 << 16);
    out[3 * (size_t)t + 1] = l0 | (h1 << 16);
    out[3 * (size_t)t + 2] = h1 | (l1 << 16);
}

__global__ void pack_wt(const float* __restrict__ W, uint32_t* __restrict__ out, int N)
{
    int t = blockIdx.x * 256 + threadIdx.x;
    if (t >= N * 384) return;
    int n = t / 384, kp = t % 384;
    float x0 = W[(size_t)(2 * kp) * N + n];
    float x1 = W[(size_t)(2 * kp + 1) * N + n];
    uint32_t h0, l0, h1, l1;
    split2(x0, h0, l0);
    split2(x1, h1, l1);
    uint32_t* o = out + (size_t)n * LDKU + 3 * kp;
    o[0] = h0 | (l0 << 16);
    o[1] = h0 | (h1 << 16);
    o[2] = l1 | (h1 << 16);
}

__global__ void zero2(float* a, int na, float* b, int nb)
{
    int t = blockIdx.x * 256 + threadIdx.x;
    if (t < na) a[t] = 0.f;
    if (t < nb) b[t] = 0.f;
}

// ---------------------------------------------------------------------------
// Middle stage: gram+norm (split over S), softmax, apply (writes packed bf16)
// ---------------------------------------------------------------------------
#define GCH 56
__global__ __launch_bounds__(256) void k_gram(
    const float* __restrict__ qkv, float* __restrict__ gram, float* __restrict__ nrm)
{
    __shared__ float qs[Dv][GCH + 1];
    __shared__ float ks[Dv][GCH + 1];
    const int bh = blockIdx.x >> 3, ck = blockIdx.x & 7;
    const int b = bh >> 4, h = bh & 15;
    const int tid = threadIdx.x;
    const size_t base = ((size_t)b * Sv + ck * 392) * 2304 + (size_t)h * Dv;

    float acc[9];
    #pragma unroll
    for (int p = 0; p < 9; p++) acc[p] = 0.f;
    float na = 0.f;

    for (int s0 = 0; s0 < 392; s0 += GCH) {
        for (int idx = tid; idx < Dv * GCH; idx += 256) {
            int i = idx % Dv, sl = idx / Dv;
            size_t g = base + (size_t)(s0 + sl) * 2304 + i;
            qs[i][sl] = qkv[g];
            ks[i][sl] = qkv[g + Ev];
        }
        __syncthreads();
        #pragma unroll
        for (int p = 0; p < 9; p++) {
            int pr = tid + p * 256;
            int i = pr / Dv, j = pr % Dv;
            float a = 0.f;
            #pragma unroll 8
            for (int sl = 0; sl < GCH; sl++) a = fmaf(qs[i][sl], ks[j][sl], a);
            acc[p] += a;
        }
        if (tid < 2 * Dv) {
            const float* row = (tid < Dv) ? qs[tid] : ks[tid - Dv];
            float a = 0.f;
            #pragma unroll 8
            for (int sl = 0; sl < GCH; sl++) a = fmaf(row[sl], row[sl], a);
            na += a;
        }
        __syncthreads();
    }
    #pragma unroll
    for (int p = 0; p < 9; p++)
        atomicAdd(gram + (size_t)bh * 2304 + tid + p * 256, acc[p]);
    if (tid < 96) atomicAdd(nrm + (size_t)bh * 96 + tid, na);
}

__global__ __launch_bounds__(256) void k_soft(
    float* __restrict__ gram, const float* __restrict__ nrm2,
    const float* __restrict__ temp)
{
    __shared__ float Gs[Dv][Dv];
    __shared__ float nr[96];
    const int bh = blockIdx.x;
    const int h = bh & 15;
    const int tid = threadIdx.x;
    for (int idx = tid; idx < 2304; idx += 256)
        Gs[idx / Dv][idx % Dv] = gram[(size_t)bh * 2304 + idx];
    if (tid < 96) nr[tid] = fmaxf(sqrtf(nrm2[(size_t)bh * 96 + tid]), 1e-12f);
    __syncthreads();
    const float T = temp[h];
    const int warp = tid >> 5, lane = tid & 31;
    for (int i = warp; i < Dv; i += 8) {
        float inq = T / nr[i];
        int j0 = lane, j1 = lane + 32;
        float v0 = Gs[i][j0] * inq / nr[Dv + j0];
        float v1 = (j1 < Dv) ? Gs[i][j1] * inq / nr[Dv + j1] : -INFINITY;
        float m = fmaxf(v0, v1);
        #pragma unroll
        for (int o = 16; o; o >>= 1) m = fmaxf(m, __shfl_xor_sync(~0u, m, o));
        float e0 = expf(v0 - m);
        float e1 = (j1 < Dv) ? expf(v1 - m) : 0.f;
        float ss = e0 + e1;
        #pragma unroll
        for (int o = 16; o; o >>= 1) ss += __shfl_xor_sync(~0u, ss, o);
        float inv = 1.f / ss;
        gram[(size_t)bh * 2304 + i * Dv + j0] = e0 * inv;
        if (j1 < Dv) gram[(size_t)bh * 2304 + i * Dv + j1] = e1 * inv;
    }
}

#define ACH 64
__global__ __launch_bounds__(256) void k_apply(
    const float* __restrict__ qkv, const float* __restrict__ attn,
    uint32_t* __restrict__ out)
{
    __shared__ float As_[Dv][Dv];
    __shared__ float vs[Dv][ACH + 1];
    const int bh = blockIdx.x / 49, ck = blockIdx.x % 49;
    const int b = bh >> 4, h = bh & 15;
    const int tid = threadIdx.x;
    for (int idx = tid; idx < 2304; idx += 256)
        As_[idx / Dv][idx % Dv] = attn[(size_t)bh * 2304 + idx];
    const size_t vbase = ((size_t)b * Sv + ck * ACH) * 2304 + 2 * Ev + (size_t)h * Dv;
    for (int idx = tid; idx < Dv * ACH; idx += 256) {
        int j = idx % Dv, sl = idx / Dv;
        vs[j][sl] = qkv[vbase + (size_t)sl * 2304 + j];
    }
    __syncthreads();
    const size_t obase = ((size_t)b * Sv + ck * ACH) * LDKU;
    for (int idx = tid; idx < 24 * ACH; idx += 256) {
        int i2 = idx % 24, sl = idx / 24;
        int i0 = 2 * i2;
        float a0 = 0.f, a1 = 0.f;
        #pragma unroll
        for (int j = 0; j < Dv; j++) {
            float v = vs[j][sl];
            a0 = fmaf(As_[i0][j], v, a0);
            a1 = fmaf(As_[i0 + 1][j], v, a1);
        }
        uint32_t h0, l0, h1, l1;
        split2(a0, h0, l0);
        split2(a1, h1, l1);
        uint32_t* o = out + obase + (size_t)sl * LDKU + 3 * (h * 24 + i2);
        o[0] = h0 | (h0 << 16);
        o[1] = l0 | (h1 << 16);
        o[2] = h1 | (l1 << 16);
    }
}

// ---------------------------------------------------------------------------
// Launch
// ---------------------------------------------------------------------------
extern "C" void kernel_launch(void* const* d_in, const int* in_sizes, int n_in,
                              void* d_out, int out_size)
{
    const float* x      = (const float*)d_in[0];
    const float* W_qkv  = (const float*)d_in[1];
    const float* W_proj = (const float*)d_in[2];
    const float* b_proj = (const float*)d_in[3];
    const float* temp   = (const float*)d_in[4];
    float* outp = (float*)d_out;

    uint32_t *x2, *mid2, *wt1, *wt2;
    float *qkv, *gram, *nrm;
    cudaGetSymbolAddress((void**)&x2, g_x2);
    cudaGetSymbolAddress((void**)&mid2, g_mid2);
    cudaGetSymbolAddress((void**)&wt1, g_wt1);
    cudaGetSymbolAddress((void**)&wt2, g_wt2);
    cudaGetSymbolAddress((void**)&qkv, g_qkv);
    cudaGetSymbolAddress((void**)&gram, g_gram);
    cudaGetSymbolAddress((void**)&nrm, g_nrm);

    cudaFuncSetAttribute(gemm_mma, cudaFuncAttributeMaxDynamicSharedMemorySize,
                         GEMM_SMEM);

    int npairs = NTOK * 384;
    pack_act<<<npairs / 256, 256>>>(x, x2, npairs);
    pack_wt<<<(2304 * 384) / 256, 256>>>(W_qkv, wt1, 2304);
    pack_wt<<<(768 * 384) / 256, 256>>>(W_proj, wt2, 768);
    // GEMM1: qkv = x @ W_qkv   [50176 x 2304]
    gemm_mma<<<392 * 18, 256, GEMM_SMEM>>>((const char*)x2, (const char*)wt1,
                                           qkv, nullptr, 2304, 18);
    // middle
    zero2<<<(256 * 2304 + 255) / 256, 256>>>(gram, 256 * 2304, nrm, 256 * 96);
    k_gram<<<256 * 8, 256>>>(qkv, gram, nrm);
    k_soft<<<256, 256>>>(gram, nrm, temp);
    k_apply<<<256 * 49, 256>>>(qkv, gram, mid2);
    // GEMM2: out = mid @ W_proj + b_proj   [50176 x 768]
    gemm_mma<<<392 * 6, 256, GEMM_SMEM>>>((const char*)mid2, (const char*)wt2,
                                          outp, b_proj, 768, 6);
}

// round 6
// speedup vs baseline: 1.6857x; 1.1174x over previous
#include <cuda_runtime.h>
#include <cuda_bf16.h>
#include <math.h>
#include <stdint.h>

// ---------------- problem constants ----------------
#define Bv 16
#define Sv 3136
#define Ev 768
#define Hv 16
#define Dv 48
#define NTOK (Bv * Sv)      // 50176
#define KPP 2304            // tripled K in bf16 elems (3 * 768)
#define LDK 4608            // bytes per packed row (KPP * 2)
#define LDKU 1152           // u32 per packed row
#define NKCH 36             // K chunks of 64 bf16 (128 bytes)
#define NSTG 3
#define STG_BYTES 32768     // 16KB A + 16KB B per stage
#define GEMM_SMEM (NSTG * STG_BYTES)   // 98304

// ---------------- scratch (device globals; no allocation allowed) ----------
__device__ uint32_t g_x2[(size_t)NTOK * LDKU];     // packed bf16 triplets of x
__device__ float    g_qkv[(size_t)NTOK * 2304];    // fp32 qkv = x @ W_qkv
__device__ uint32_t g_mid2[(size_t)NTOK * LDKU];   // packed bf16 triplets of mid
__device__ uint32_t g_wt1[(size_t)2304 * LDKU];    // W_qkv^T packed (B layout)
__device__ uint32_t g_wt2[(size_t)768 * LDKU];     // W_proj^T packed
__device__ float    g_gram[256 * 2304];            // per (b,h) 48x48 gram / attn
__device__ float    g_nrm[256 * 96];               // per (b,h) squared norms

// ---------------- helpers ----------------
__device__ __forceinline__ uint32_t s2u(const void* p) {
    uint32_t a;
    asm("{ .reg .u64 t; cvta.to.shared.u64 t, %1; cvt.u32.u64 %0, t; }"
        : "=r"(a) : "l"(p));
    return a;
}
#define SWZ(o) ((o) ^ (((o) >> 3) & 0x70))

__device__ __forceinline__ void cpasync16(uint32_t s, const void* g) {
    asm volatile("cp.async.cg.shared.global [%0], [%1], 16;\n" :: "r"(s), "l"(g));
}
__device__ __forceinline__ void cp_commit() {
    asm volatile("cp.async.commit_group;\n");
}
template <int N> __device__ __forceinline__ void cp_wait() {
    asm volatile("cp.async.wait_group %0;\n" :: "n"(N));
}
__device__ __forceinline__ void ldm4(uint32_t& r0, uint32_t& r1, uint32_t& r2,
                                     uint32_t& r3, uint32_t a) {
    asm volatile("ldmatrix.sync.aligned.m8n8.x4.shared.b16 {%0,%1,%2,%3}, [%4];"
                 : "=r"(r0), "=r"(r1), "=r"(r2), "=r"(r3) : "r"(a));
}
__device__ __forceinline__ void mma16816(float* d, const uint32_t* a,
                                         const uint32_t* b) {
    asm volatile(
        "mma.sync.aligned.m16n8k16.row.col.f32.bf16.bf16.f32 "
        "{%0,%1,%2,%3}, {%4,%5,%6,%7}, {%8,%9}, {%0,%1,%2,%3};"
        : "+f"(d[0]), "+f"(d[1]), "+f"(d[2]), "+f"(d[3])
        : "r"(a[0]), "r"(a[1]), "r"(a[2]), "r"(a[3]), "r"(b[0]), "r"(b[1]));
}
__device__ __forceinline__ void split2(float x, uint32_t& h, uint32_t& l) {
    __nv_bfloat16 hb = __float2bfloat16(x);
    float rem = x - __bfloat162float(hb);
    __nv_bfloat16 lb = __float2bfloat16(rem);
    h = (uint32_t)__bfloat16_as_ushort(hb);
    l = (uint32_t)__bfloat16_as_ushort(lb);
}

// ---------------------------------------------------------------------------
// bf16 mma.sync GEMM: C[M,N] (fp32) = A'' @ B''^T over packed triplet K.
// CTA tile 128x128, BK=64 bf16, 4 warps of 64x64 (halves LDSM bytes/FLOP vs
// 8x(32x64)). 3-stage cp.async pipeline, fragment double-buffering, one
// __syncthreads per k chunk. 2 CTAs/SM (96KB smem each, <=255 regs).
// ---------------------------------------------------------------------------
__global__ __launch_bounds__(128, 2) void gemm_mma(
    const char* __restrict__ A, const char* __restrict__ B,
    float* __restrict__ C, const float* __restrict__ bias, int N, int NT)
{
    extern __shared__ char sm[];
    const int tid  = threadIdx.x;
    const int wid  = tid >> 5, lane = tid & 31;
    const int wm   = wid & 1;          // warp m half (64 rows)
    const int wn   = wid >> 1;         // warp n half (64 cols)
    const int bm   = blockIdx.x / NT, bn = blockIdx.x % NT;
    const uint32_t smb = s2u(sm);

    const char* Ab = A + (size_t)bm * 128 * LDK;
    const char* Bb = B + (size_t)bn * 128 * LDK;

    const int ldr = tid;               // 0..127: one row of A and B per thread

    auto loadch = [&](int sp, int ck) {
        uint32_t sa = smb + sp * STG_BYTES;
        uint32_t sb = sa + 16384;
        const char* a0 = Ab + ck * 128 + (size_t)ldr * LDK;
        const char* b0 = Bb + ck * 128 + (size_t)ldr * LDK;
        #pragma unroll
        for (int i = 0; i < 8; i++) {
            cpasync16(sa + SWZ(ldr * 128 + i * 16), a0 + i * 16);
            cpasync16(sb + SWZ(ldr * 128 + i * 16), b0 + i * 16);
        }
        cp_commit();
    };

    float acc[4][8][4];
    #pragma unroll
    for (int m = 0; m < 4; m++)
        #pragma unroll
        for (int n = 0; n < 8; n++)
            #pragma unroll
            for (int p = 0; p < 4; p++) acc[m][n][p] = 0.f;

    loadch(0, 0);
    loadch(1, 1);

    // per-lane ldmatrix address pieces (same mapping as validated rounds 4-5)
    const int a_row = (lane & 7) + ((lane >> 3) & 1) * 8;
    const int a_cb  = (lane >> 4) * 16;
    const int b_row = (lane & 7) + (lane >> 4) * 8;
    const int b_cb  = ((lane >> 3) & 1) * 16;

    uint32_t af[2][4][4], bf[2][8][2];

    auto ldfrag = [&](uint32_t sa, uint32_t sb, int ks, int buf) {
        #pragma unroll
        for (int mb = 0; mb < 4; mb++) {
            int r = wm * 64 + mb * 16 + a_row;
            ldm4(af[buf][mb][0], af[buf][mb][1], af[buf][mb][2], af[buf][mb][3],
                 sa + SWZ(r * 128 + ks * 32 + a_cb));
        }
        #pragma unroll
        for (int nb2 = 0; nb2 < 4; nb2++) {
            int r = wn * 64 + nb2 * 16 + b_row;
            ldm4(bf[buf][2 * nb2][0], bf[buf][2 * nb2][1],
                 bf[buf][2 * nb2 + 1][0], bf[buf][2 * nb2 + 1][1],
                 sb + SWZ(r * 128 + ks * 32 + b_cb));
        }
    };

    for (int k = 0; k < NKCH; k++) {
        cp_wait<1>();          // group k complete
        __syncthreads();       // publishes stage k%3; proves stage (k-1)%3 free

        int kp = k + 2;
        if (kp < NKCH) loadch(kp % NSTG, kp);
        else cp_commit();

        uint32_t sa = smb + (k % NSTG) * STG_BYTES;
        uint32_t sb = sa + 16384;

        ldfrag(sa, sb, 0, 0);
        #pragma unroll
        for (int ks = 0; ks < 4; ks++) {
            int c = ks & 1;
            if (ks < 3) ldfrag(sa, sb, ks + 1, c ^ 1);
            #pragma unroll
            for (int mb = 0; mb < 4; mb++)
                #pragma unroll
                for (int nb = 0; nb < 8; nb++)
                    mma16816(acc[mb][nb], af[c][mb], bf[c][nb]);
        }
    }

    // Epilogue: registers -> global
    float* Cb = C + (size_t)(bm * 128 + wm * 64) * N + (size_t)bn * 128 + wn * 64;
    const int er = lane >> 2;
    const int ec = (lane & 3) * 2;
    float bvs[8][2];
    #pragma unroll
    for (int nb = 0; nb < 8; nb++) {
        if (bias) {
            const float* bp = bias + (size_t)bn * 128 + wn * 64 + nb * 8 + ec;
            bvs[nb][0] = bp[0]; bvs[nb][1] = bp[1];
        } else { bvs[nb][0] = 0.f; bvs[nb][1] = 0.f; }
    }
    #pragma unroll
    for (int mb = 0; mb < 4; mb++) {
        #pragma unroll
        for (int nb = 0; nb < 8; nb++) {
            int col = nb * 8 + ec;
            float2 v0 = {acc[mb][nb][0] + bvs[nb][0], acc[mb][nb][1] + bvs[nb][1]};
            float2 v1 = {acc[mb][nb][2] + bvs[nb][0], acc[mb][nb][3] + bvs[nb][1]};
            *(float2*)(Cb + (size_t)(mb * 16 + er) * N + col) = v0;
            *(float2*)(Cb + (size_t)(mb * 16 + er + 8) * N + col) = v1;
        }
    }
}

// ---------------------------------------------------------------------------
// Conversion kernels (fp32 -> bf16 hi/lo triplets)
// A layout per k: [hi, hi, lo]; B layout per k: [hi, lo, hi]
// ---------------------------------------------------------------------------
__global__ void pack_act(const float* __restrict__ in, uint32_t* __restrict__ out,
                         int npairs)
{
    int t = blockIdx.x * 256 + threadIdx.x;
    if (t >= npairs) return;
    float2 xv = ((const float2*)in)[t];
    uint32_t h0, l0, h1, l1;
    split2(xv.x, h0, l0);
    split2(xv.y, h1, l1);
    out[3 * (size_t)t + 0] = h0 | (h0 << 16);
    out[3 * (size_t)t + 1] = l0 | (h1 << 16);
    out[3 * (size_t)t + 2] = h1 | (l1 << 16);
}

__global__ void pack_wt(const float* __restrict__ W, uint32_t* __restrict__ out, int N)
{
    int t = blockIdx.x * 256 + threadIdx.x;
    if (t >= N * 384) return;
    int n = t / 384, kp = t % 384;
    float x0 = W[(size_t)(2 * kp) * N + n];
    float x1 = W[(size_t)(2 * kp + 1) * N + n];
    uint32_t h0, l0, h1, l1;
    split2(x0, h0, l0);
    split2(x1, h1, l1);
    uint32_t* o = out + (size_t)n * LDKU + 3 * kp;
    o[0] = h0 | (l0 << 16);
    o[1] = h0 | (h1 << 16);
    o[2] = l1 | (h1 << 16);
}

__global__ void zero2(float* a, int na, float* b, int nb)
{
    int t = blockIdx.x * 256 + threadIdx.x;
    if (t < na) a[t] = 0.f;
    if (t < nb) b[t] = 0.f;
}

// ---------------------------------------------------------------------------
// Middle stage. k_gram: 16x16 threads, 3x3 register block per thread
// (6 LDS per 9 FMA). k_apply: 8x32 threads, 6i x 2sl register block
// (8 LDS per 12 FMA).
// ---------------------------------------------------------------------------
#define GCH 56
__global__ __launch_bounds__(256) void k_gram(
    const float* __restrict__ qkv, float* __restrict__ gram, float* __restrict__ nrm)
{
    __shared__ float qs[Dv][GCH + 1];
    __shared__ float ks[Dv][GCH + 1];
    const int bh = blockIdx.x >> 3, ck = blockIdx.x & 7;
    const int b = bh >> 4, h = bh & 15;
    const int tid = threadIdx.x;
    const int tx = tid & 15, ty = tid >> 4;
    const size_t base = ((size_t)b * Sv + ck * 392) * 2304 + (size_t)h * Dv;

    float acc[3][3];
    #pragma unroll
    for (int r = 0; r < 3; r++)
        #pragma unroll
        for (int c = 0; c < 3; c++) acc[r][c] = 0.f;
    float na = 0.f;

    for (int s0 = 0; s0 < 392; s0 += GCH) {
        for (int idx = tid; idx < Dv * GCH; idx += 256) {
            int i = idx % Dv, sl = idx / Dv;
            size_t g = base + (size_t)(s0 + sl) * 2304 + i;
            qs[i][sl] = qkv[g];
            ks[i][sl] = qkv[g + Ev];
        }
        __syncthreads();
        #pragma unroll 4
        for (int sl = 0; sl < GCH; sl++) {
            float qv[3], kv[3];
            #pragma unroll
            for (int r = 0; r < 3; r++) qv[r] = qs[3 * ty + r][sl];
            #pragma unroll
            for (int c = 0; c < 3; c++) kv[c] = ks[3 * tx + c][sl];
            #pragma unroll
            for (int r = 0; r < 3; r++)
                #pragma unroll
                for (int c = 0; c < 3; c++)
                    acc[r][c] = fmaf(qv[r], kv[c], acc[r][c]);
        }
        if (tid < 2 * Dv) {
            const float* row = (tid < Dv) ? qs[tid] : ks[tid - Dv];
            float a = 0.f;
            #pragma unroll 8
            for (int sl = 0; sl < GCH; sl++) a = fmaf(row[sl], row[sl], a);
            na += a;
        }
        __syncthreads();
    }
    #pragma unroll
    for (int r = 0; r < 3; r++)
        #pragma unroll
        for (int c = 0; c < 3; c++)
            atomicAdd(gram + (size_t)bh * 2304 + (3 * ty + r) * Dv + 3 * tx + c,
                      acc[r][c]);
    if (tid < 96) atomicAdd(nrm + (size_t)bh * 96 + tid, na);
}

__global__ __launch_bounds__(256) void k_soft(
    float* __restrict__ gram, const float* __restrict__ nrm2,
    const float* __restrict__ temp)
{
    __shared__ float Gs[Dv][Dv];
    __shared__ float nr[96];
    const int bh = blockIdx.x;
    const int h = bh & 15;
    const int tid = threadIdx.x;
    for (int idx = tid; idx < 2304; idx += 256)
        Gs[idx / Dv][idx % Dv] = gram[(size_t)bh * 2304 + idx];
    if (tid < 96) nr[tid] = fmaxf(sqrtf(nrm2[(size_t)bh * 96 + tid]), 1e-12f);
    __syncthreads();
    const float T = temp[h];
    const int warp = tid >> 5, lane = tid & 31;
    for (int i = warp; i < Dv; i += 8) {
        float inq = T / nr[i];
        int j0 = lane, j1 = lane + 32;
        float v0 = Gs[i][j0] * inq / nr[Dv + j0];
        float v1 = (j1 < Dv) ? Gs[i][j1] * inq / nr[Dv + j1] : -INFINITY;
        float m = fmaxf(v0, v1);
        #pragma unroll
        for (int o = 16; o; o >>= 1) m = fmaxf(m, __shfl_xor_sync(~0u, m, o));
        float e0 = expf(v0 - m);
        float e1 = (j1 < Dv) ? expf(v1 - m) : 0.f;
        float ss = e0 + e1;
        #pragma unroll
        for (int o = 16; o; o >>= 1) ss += __shfl_xor_sync(~0u, ss, o);
        float inv = 1.f / ss;
        gram[(size_t)bh * 2304 + i * Dv + j0] = e0 * inv;
        if (j1 < Dv) gram[(size_t)bh * 2304 + i * Dv + j1] = e1 * inv;
    }
}

#define ACH 64
__global__ __launch_bounds__(256) void k_apply(
    const float* __restrict__ qkv, const float* __restrict__ attn,
    uint32_t* __restrict__ out)
{
    __shared__ float As_[Dv][Dv + 1];
    __shared__ float vs[Dv][ACH + 1];
    const int bh = blockIdx.x / 49, ck = blockIdx.x % 49;
    const int b = bh >> 4, h = bh & 15;
    const int tid = threadIdx.x;
    const int ti = tid & 7;     // i block: 6 rows
    const int ts = tid >> 3;    // sl block: 2 tokens
    for (int idx = tid; idx < 2304; idx += 256)
        As_[idx / Dv][idx % Dv] = attn[(size_t)bh * 2304 + idx];
    const size_t vbase = ((size_t)b * Sv + ck * ACH) * 2304 + 2 * Ev + (size_t)h * Dv;
    for (int idx = tid; idx < Dv * ACH; idx += 256) {
        int j = idx % Dv, sl = idx / Dv;
        vs[j][sl] = qkv[vbase + (size_t)sl * 2304 + j];
    }
    __syncthreads();

    float acc[6][2];
    #pragma unroll
    for (int r = 0; r < 6; r++) { acc[r][0] = 0.f; acc[r][1] = 0.f; }
    #pragma unroll 4
    for (int j = 0; j < Dv; j++) {
        float v0 = vs[j][2 * ts + 0];
        float v1 = vs[j][2 * ts + 1];
        #pragma unroll
        for (int r = 0; r < 6; r++) {
            float a = As_[6 * ti + r][j];
            acc[r][0] = fmaf(a, v0, acc[r][0]);
            acc[r][1] = fmaf(a, v1, acc[r][1]);
        }
    }

    const size_t obase = ((size_t)b * Sv + ck * ACH) * LDKU;
    #pragma unroll
    for (int c = 0; c < 2; c++) {
        int sl = 2 * ts + c;
        #pragma unroll
        for (int p = 0; p < 3; p++) {
            int i0 = 6 * ti + 2 * p;
            uint32_t h0, l0, h1, l1;
            split2(acc[2 * p][c], h0, l0);
            split2(acc[2 * p + 1][c], h1, l1);
            uint32_t* o = out + obase + (size_t)sl * LDKU + 3 * (h * 24 + i0 / 2);
            o[0] = h0 | (h0 << 16);
            o[1] = l0 | (h1 << 16);
            o[2] = h1 | (l1 << 16);
        }
    }
}

// ---------------------------------------------------------------------------
// Launch
// ---------------------------------------------------------------------------
extern "C" void kernel_launch(void* const* d_in, const int* in_sizes, int n_in,
                              void* d_out, int out_size)
{
    const float* x      = (const float*)d_in[0];
    const float* W_qkv  = (const float*)d_in[1];
    const float* W_proj = (const float*)d_in[2];
    const float* b_proj = (const float*)d_in[3];
    const float* temp   = (const float*)d_in[4];
    float* outp = (float*)d_out;

    uint32_t *x2, *mid2, *wt1, *wt2;
    float *qkv, *gram, *nrm;
    cudaGetSymbolAddress((void**)&x2, g_x2);
    cudaGetSymbolAddress((void**)&mid2, g_mid2);
    cudaGetSymbolAddress((void**)&wt1, g_wt1);
    cudaGetSymbolAddress((void**)&wt2, g_wt2);
    cudaGetSymbolAddress((void**)&qkv, g_qkv);
    cudaGetSymbolAddress((void**)&gram, g_gram);
    cudaGetSymbolAddress((void**)&nrm, g_nrm);

    cudaFuncSetAttribute(gemm_mma, cudaFuncAttributeMaxDynamicSharedMemorySize,
                         GEMM_SMEM);

    int npairs = NTOK * 384;
    pack_act<<<npairs / 256, 256>>>(x, x2, npairs);
    pack_wt<<<(2304 * 384) / 256, 256>>>(W_qkv, wt1, 2304);
    pack_wt<<<(768 * 384) / 256, 256>>>(W_proj, wt2, 768);
    // GEMM1: qkv = x @ W_qkv   [50176 x 2304]
    gemm_mma<<<392 * 18, 128, GEMM_SMEM>>>((const char*)x2, (const char*)wt1,
                                           qkv, nullptr, 2304, 18);
    // middle
    zero2<<<(256 * 2304 + 255) / 256, 256>>>(gram, 256 * 2304, nrm, 256 * 96);
    k_gram<<<256 * 8, 256>>>(qkv, gram, nrm);
    k_soft<<<256, 256>>>(gram, nrm, temp);
    k_apply<<<256 * 49, 256>>>(qkv, gram, mid2);
    // GEMM2: out = mid @ W_proj + b_proj   [50176 x 768]
    gemm_mma<<<392 * 6, 128, GEMM_SMEM>>>((const char*)mid2, (const char*)wt2,
                                          outp, b_proj, 768, 6);
}

// round 8
// speedup vs baseline: 2.3553x; 1.3972x over previous
#include <cuda_runtime.h>
#include <cuda_bf16.h>
#include <math.h>
#include <stdint.h>

// ---------------- problem constants ----------------
#define Bv 16
#define Sv 3136
#define Ev 768
#define Hv 16
#define Dv 48
#define NTOK (Bv * Sv)      // 50176
#define KPP 2304            // tripled K in bf16 elems (3 * 768)
#define LDK 4608            // bytes per packed row (KPP * 2)
#define LDKU 1152           // u32 per packed row
#define NKCH 36             // K chunks of 64 bf16 (128 bytes)
#define NSTG 3
#define STG_BYTES 32768     // 16KB A + 16KB B per stage
#define GEMM_SMEM (NSTG * STG_BYTES)   // 98304

// ---------------- scratch (device globals; no allocation allowed) ----------
__device__ uint32_t g_x2[(size_t)NTOK * LDKU];     // packed bf16 triplets of x
__device__ float    g_qkv[(size_t)NTOK * 2304];    // fp32 qkv = x @ W_qkv
__device__ uint32_t g_mid2[(size_t)NTOK * LDKU];   // packed bf16 triplets of mid
__device__ uint32_t g_wt1[(size_t)2304 * LDKU];    // W_qkv^T packed (B layout)
__device__ uint32_t g_wt2[(size_t)768 * LDKU];     // W_proj^T packed
__device__ float    g_gram[256 * 2304];            // per (b,h) 48x48 gram / attn
__device__ float    g_nrm[256 * 96];               // per (b,h) squared norms

// ---------------- helpers ----------------
__device__ __forceinline__ uint32_t s2u(const void* p) {
    uint32_t a;
    asm("{ .reg .u64 t; cvta.to.shared.u64 t, %1; cvt.u32.u64 %0, t; }"
        : "=r"(a) : "l"(p));
    return a;
}
#define SWZ(o) ((o) ^ (((o) >> 3) & 0x70))

__device__ __forceinline__ void cpasync16(uint32_t s, const void* g) {
    asm volatile("cp.async.cg.shared.global [%0], [%1], 16;\n" :: "r"(s), "l"(g));
}
__device__ __forceinline__ void cp_commit() {
    asm volatile("cp.async.commit_group;\n");
}
template <int N> __device__ __forceinline__ void cp_wait() {
    asm volatile("cp.async.wait_group %0;\n" :: "n"(N));
}
__device__ __forceinline__ void ldm4(uint32_t& r0, uint32_t& r1, uint32_t& r2,
                                     uint32_t& r3, uint32_t a) {
    asm volatile("ldmatrix.sync.aligned.m8n8.x4.shared.b16 {%0,%1,%2,%3}, [%4];"
                 : "=r"(r0), "=r"(r1), "=r"(r2), "=r"(r3) : "r"(a));
}
__device__ __forceinline__ void mma16816(float* d, const uint32_t* a,
                                         const uint32_t* b) {
    asm volatile(
        "mma.sync.aligned.m16n8k16.row.col.f32.bf16.bf16.f32 "
        "{%0,%1,%2,%3}, {%4,%5,%6,%7}, {%8,%9}, {%0,%1,%2,%3};"
        : "+f"(d[0]), "+f"(d[1]), "+f"(d[2]), "+f"(d[3])
        : "r"(a[0]), "r"(a[1]), "r"(a[2]), "r"(a[3]), "r"(b[0]), "r"(b[1]));
}
__device__ __forceinline__ void split2(float x, uint32_t& h, uint32_t& l) {
    __nv_bfloat16 hb = __float2bfloat16(x);
    float rem = x - __bfloat162float(hb);
    __nv_bfloat16 lb = __float2bfloat16(rem);
    h = (uint32_t)__bfloat16_as_ushort(hb);
    l = (uint32_t)__bfloat16_as_ushort(lb);
}

// ---------------------------------------------------------------------------
// bf16 mma.sync GEMM (round-5 proven config): CTA tile 128x128, BK=64 bf16,
// 8 warps of 32x64, 3-stage cp.async pipeline, fragment double-buffering,
// one __syncthreads per k chunk, 128 regs -> 2 CTAs/SM (16 warps).
// ---------------------------------------------------------------------------
__global__ __launch_bounds__(256, 2) void gemm_mma(
    const char* __restrict__ A, const char* __restrict__ B,
    float* __restrict__ C, const float* __restrict__ bias, int N, int NT)
{
    extern __shared__ char sm[];
    const int tid  = threadIdx.x;
    const int wid  = tid >> 5, lane = tid & 31;
    const int wm   = wid & 3;          // warp m index (0-3), 32 rows each
    const int wn   = wid >> 2;         // warp n index (0-1), 64 cols each
    const int bm   = blockIdx.x / NT, bn = blockIdx.x % NT;
    const uint32_t smb = s2u(sm);

    const char* Ab = A + (size_t)bm * 128 * LDK;
    const char* Bb = B + (size_t)bn * 128 * LDK;

    const int ldr = tid >> 1;              // 0..127 row
    const int ldc = (tid & 1) * 64;        // byte col 0 or 64

    auto loadch = [&](int sp, int ck) {
        uint32_t sa = smb + sp * STG_BYTES;
        uint32_t sb = sa + 16384;
        const char* a0 = Ab + ck * 128;
        const char* b0 = Bb + ck * 128;
        #pragma unroll
        for (int i = 0; i < 4; i++) {
            int cb = ldc + i * 16;
            cpasync16(sa + SWZ(ldr * 128 + cb), a0 + (size_t)ldr * LDK + cb);
            cpasync16(sb + SWZ(ldr * 128 + cb), b0 + (size_t)ldr * LDK + cb);
        }
        cp_commit();
    };

    float acc[2][8][4];
    #pragma unroll
    for (int m = 0; m < 2; m++)
        #pragma unroll
        for (int n = 0; n < 8; n++)
            #pragma unroll
            for (int p = 0; p < 4; p++) acc[m][n][p] = 0.f;

    loadch(0, 0);
    loadch(1, 1);

    const int a_row = (lane & 7) + ((lane >> 3) & 1) * 8;
    const int a_cb  = (lane >> 4) * 16;
    const int b_row = (lane & 7) + (lane >> 4) * 8;
    const int b_cb  = ((lane >> 3) & 1) * 16;

    uint32_t af[2][2][4], bf[2][8][2];

    auto ldfrag = [&](uint32_t sa, uint32_t sb, int ks, int buf) {
        #pragma unroll
        for (int mb = 0; mb < 2; mb++) {
            int r = wm * 32 + mb * 16 + a_row;
            ldm4(af[buf][mb][0], af[buf][mb][1], af[buf][mb][2], af[buf][mb][3],
                 sa + SWZ(r * 128 + ks * 32 + a_cb));
        }
        #pragma unroll
        for (int nb2 = 0; nb2 < 4; nb2++) {
            int r = wn * 64 + nb2 * 16 + b_row;
            ldm4(bf[buf][2 * nb2][0], bf[buf][2 * nb2][1],
                 bf[buf][2 * nb2 + 1][0], bf[buf][2 * nb2 + 1][1],
                 sb + SWZ(r * 128 + ks * 32 + b_cb));
        }
    };

    for (int k = 0; k < NKCH; k++) {
        cp_wait<1>();          // group k complete
        __syncthreads();       // publishes stage k%3; proves stage (k-1)%3 free

        int kp = k + 2;
        if (kp < NKCH) loadch(kp % NSTG, kp);
        else cp_commit();

        uint32_t sa = smb + (k % NSTG) * STG_BYTES;
        uint32_t sb = sa + 16384;

        ldfrag(sa, sb, 0, 0);
        #pragma unroll
        for (int ks = 0; ks < 4; ks++) {
            int c = ks & 1;
            if (ks < 3) ldfrag(sa, sb, ks + 1, c ^ 1);
            #pragma unroll
            for (int mb = 0; mb < 2; mb++)
                #pragma unroll
                for (int nb = 0; nb < 8; nb++)
                    mma16816(acc[mb][nb], af[c][mb], bf[c][nb]);
        }
    }

    // Epilogue: registers -> global
    float* Cb = C + (size_t)(bm * 128 + wm * 32) * N + (size_t)bn * 128 + wn * 64;
    const int er = lane >> 2;
    const int ec = (lane & 3) * 2;
    float bvs[8][2];
    #pragma unroll
    for (int nb = 0; nb < 8; nb++) {
        if (bias) {
            const float* bp = bias + (size_t)bn * 128 + wn * 64 + nb * 8 + ec;
            bvs[nb][0] = bp[0]; bvs[nb][1] = bp[1];
        } else { bvs[nb][0] = 0.f; bvs[nb][1] = 0.f; }
    }
    #pragma unroll
    for (int mb = 0; mb < 2; mb++) {
        #pragma unroll
        for (int nb = 0; nb < 8; nb++) {
            int col = nb * 8 + ec;
            float2 v0 = {acc[mb][nb][0] + bvs[nb][0], acc[mb][nb][1] + bvs[nb][1]};
            float2 v1 = {acc[mb][nb][2] + bvs[nb][0], acc[mb][nb][3] + bvs[nb][1]};
            *(float2*)(Cb + (size_t)(mb * 16 + er) * N + col) = v0;
            *(float2*)(Cb + (size_t)(mb * 16 + er + 8) * N + col) = v1;
        }
    }
}

// ---------------------------------------------------------------------------
// Conversion kernels (fp32 -> bf16 hi/lo triplets)
// A layout per k: [hi, hi, lo]; B layout per k: [hi, lo, hi]
// ---------------------------------------------------------------------------
__global__ void pack_act(const float* __restrict__ in, uint32_t* __restrict__ out,
                         int npairs)
{
    int t = blockIdx.x * 256 + threadIdx.x;
    if (t >= npairs) return;
    float2 xv = ((const float2*)in)[t];
    uint32_t h0, l0, h1, l1;
    split2(xv.x, h0, l0);
    split2(xv.y, h1, l1);
    out[3 * (size_t)t + 0] = h0 | (h0 << 16);
    out[3 * (size_t)t + 1] = l0 | (h1 << 16);
    out[3 * (size_t)t + 2] = h1 | (l1 << 16);
}

__global__ void pack_wt(const float* __restrict__ W, uint32_t* __restrict__ out, int N)
{
    int t = blockIdx.x * 256 + threadIdx.x;
    if (t >= N * 384) return;
    int n = t / 384, kp = t % 384;
    float x0 = W[(size_t)(2 * kp) * N + n];
    float x1 = W[(size_t)(2 * kp + 1) * N + n];
    uint32_t h0, l0, h1, l1;
    split2(x0, h0, l0);
    split2(x1, h1, l1);
    uint32_t* o = out + (size_t)n * LDKU + 3 * kp;
    o[0] = h0 | (l0 << 16);
    o[1] = h0 | (h1 << 16);
    o[2] = l1 | (h1 << 16);
}

__global__ void zero2(float* a, int na, float* b, int nb)
{
    int t = blockIdx.x * 256 + threadIdx.x;
    if (t < na) a[t] = 0.f;
    if (t < nb) b[t] = 0.f;
}

// ---------------------------------------------------------------------------
// Middle stage (round-6 proven). k_gram: 3x3 register block per thread.
// k_apply: 6i x 2sl register block per thread, writes packed bf16 triplets.
// ---------------------------------------------------------------------------
#define GCH 56
__global__ __launch_bounds__(256) void k_gram(
    const float* __restrict__ qkv, float* __restrict__ gram, float* __restrict__ nrm)
{
    __shared__ float qs[Dv][GCH + 1];
    __shared__ float ks[Dv][GCH + 1];
    const int bh = blockIdx.x >> 3, ck = blockIdx.x & 7;
    const int b = bh >> 4, h = bh & 15;
    const int tid = threadIdx.x;
    const int tx = tid & 15, ty = tid >> 4;
    const size_t base = ((size_t)b * Sv + ck * 392) * 2304 + (size_t)h * Dv;

    float acc[3][3];
    #pragma unroll
    for (int r = 0; r < 3; r++)
        #pragma unroll
        for (int c = 0; c < 3; c++) acc[r][c] = 0.f;
    float na = 0.f;

    for (int s0 = 0; s0 < 392; s0 += GCH) {
        for (int idx = tid; idx < Dv * GCH; idx += 256) {
            int i = idx % Dv, sl = idx / Dv;
            size_t g = base + (size_t)(s0 + sl) * 2304 + i;
            qs[i][sl] = qkv[g];
            ks[i][sl] = qkv[g + Ev];
        }
        __syncthreads();
        #pragma unroll 4
        for (int sl = 0; sl < GCH; sl++) {
            float qv[3], kv[3];
            #pragma unroll
            for (int r = 0; r < 3; r++) qv[r] = qs[3 * ty + r][sl];
            #pragma unroll
            for (int c = 0; c < 3; c++) kv[c] = ks[3 * tx + c][sl];
            #pragma unroll
            for (int r = 0; r < 3; r++)
                #pragma unroll
                for (int c = 0; c < 3; c++)
                    acc[r][c] = fmaf(qv[r], kv[c], acc[r][c]);
        }
        if (tid < 2 * Dv) {
            const float* row = (tid < Dv) ? qs[tid] : ks[tid - Dv];
            float a = 0.f;
            #pragma unroll 8
            for (int sl = 0; sl < GCH; sl++) a = fmaf(row[sl], row[sl], a);
            na += a;
        }
        __syncthreads();
    }
    #pragma unroll
    for (int r = 0; r < 3; r++)
        #pragma unroll
        for (int c = 0; c < 3; c++)
            atomicAdd(gram + (size_t)bh * 2304 + (3 * ty + r) * Dv + 3 * tx + c,
                      acc[r][c]);
    if (tid < 96) atomicAdd(nrm + (size_t)bh * 96 + tid, na);
}

__global__ __launch_bounds__(256) void k_soft(
    float* __restrict__ gram, const float* __restrict__ nrm2,
    const float* __restrict__ temp)
{
    __shared__ float Gs[Dv][Dv];
    __shared__ float nr[96];
    const int bh = blockIdx.x;
    const int h = bh & 15;
    const int tid = threadIdx.x;
    for (int idx = tid; idx < 2304; idx += 256)
        Gs[idx / Dv][idx % Dv] = gram[(size_t)bh * 2304 + idx];
    if (tid < 96) nr[tid] = fmaxf(sqrtf(nrm2[(size_t)bh * 96 + tid]), 1e-12f);
    __syncthreads();
    const float T = temp[h];
    const int warp = tid >> 5, lane = tid & 31;
    for (int i = warp; i < Dv; i += 8) {
        float inq = T / nr[i];
        int j0 = lane, j1 = lane + 32;
        float v0 = Gs[i][j0] * inq / nr[Dv + j0];
        float v1 = (j1 < Dv) ? Gs[i][j1] * inq / nr[Dv + j1] : -INFINITY;
        float m = fmaxf(v0, v1);
        #pragma unroll
        for (int o = 16; o; o >>= 1) m = fmaxf(m, __shfl_xor_sync(~0u, m, o));
        float e0 = expf(v0 - m);
        float e1 = (j1 < Dv) ? expf(v1 - m) : 0.f;
        float ss = e0 + e1;
        #pragma unroll
        for (int o = 16; o; o >>= 1) ss += __shfl_xor_sync(~0u, ss, o);
        float inv = 1.f / ss;
        gram[(size_t)bh * 2304 + i * Dv + j0] = e0 * inv;
        if (j1 < Dv) gram[(size_t)bh * 2304 + i * Dv + j1] = e1 * inv;
    }
}

#define ACH 64
__global__ __launch_bounds__(256) void k_apply(
    const float* __restrict__ qkv, const float* __restrict__ attn,
    uint32_t* __restrict__ out)
{
    __shared__ float As_[Dv][Dv + 1];
    __shared__ float vs[Dv][ACH + 1];
    const int bh = blockIdx.x / 49, ck = blockIdx.x % 49;
    const int b = bh >> 4, h = bh & 15;
    const int tid = threadIdx.x;
    const int ti = tid & 7;     // i block: 6 rows
    const int ts = tid >> 3;    // sl block: 2 tokens
    for (int idx = tid; idx < 2304; idx += 256)
        As_[idx / Dv][idx % Dv] = attn[(size_t)bh * 2304 + idx];
    const size_t vbase = ((size_t)b * Sv + ck * ACH) * 2304 + 2 * Ev + (size_t)h * Dv;
    for (int idx = tid; idx < Dv * ACH; idx += 256) {
        int j = idx % Dv, sl = idx / Dv;
        vs[j][sl] = qkv[vbase + (size_t)sl * 2304 + j];
    }
    __syncthreads();

    float acc[6][2];
    #pragma unroll
    for (int r = 0; r < 6; r++) { acc[r][0] = 0.f; acc[r][1] = 0.f; }
    #pragma unroll 4
    for (int j = 0; j < Dv; j++) {
        float v0 = vs[j][2 * ts + 0];
        float v1 = vs[j][2 * ts + 1];
        #pragma unroll
        for (int r = 0; r < 6; r++) {
            float a = As_[6 * ti + r][j];
            acc[r][0] = fmaf(a, v0, acc[r][0]);
            acc[r][1] = fmaf(a, v1, acc[r][1]);
        }
    }

    const size_t obase = ((size_t)b * Sv + ck * ACH) * LDKU;
    #pragma unroll
    for (int c = 0; c < 2; c++) {
        int sl = 2 * ts + c;
        #pragma unroll
        for (int p = 0; p < 3; p++) {
            int i0 = 6 * ti + 2 * p;
            uint32_t h0, l0, h1, l1;
            split2(acc[2 * p][c], h0, l0);
            split2(acc[2 * p + 1][c], h1, l1);
            uint32_t* o = out + obase + (size_t)sl * LDKU + 3 * (h * 24 + i0 / 2);
            o[0] = h0 | (h0 << 16);
            o[1] = l0 | (h1 << 16);
            o[2] = h1 | (l1 << 16);
        }
    }
}

// ---------------------------------------------------------------------------
// Launch
// ---------------------------------------------------------------------------
extern "C" void kernel_launch(void* const* d_in, const int* in_sizes, int n_in,
                              void* d_out, int out_size)
{
    const float* x      = (const float*)d_in[0];
    const float* W_qkv  = (const float*)d_in[1];
    const float* W_proj = (const float*)d_in[2];
    const float* b_proj = (const float*)d_in[3];
    const float* temp   = (const float*)d_in[4];
    float* outp = (float*)d_out;

    uint32_t *x2, *mid2, *wt1, *wt2;
    float *qkv, *gram, *nrm;
    cudaGetSymbolAddress((void**)&x2, g_x2);
    cudaGetSymbolAddress((void**)&mid2, g_mid2);
    cudaGetSymbolAddress((void**)&wt1, g_wt1);
    cudaGetSymbolAddress((void**)&wt2, g_wt2);
    cudaGetSymbolAddress((void**)&qkv, g_qkv);
    cudaGetSymbolAddress((void**)&gram, g_gram);
    cudaGetSymbolAddress((void**)&nrm, g_nrm);

    cudaFuncSetAttribute(gemm_mma, cudaFuncAttributeMaxDynamicSharedMemorySize,
                         GEMM_SMEM);

    int npairs = NTOK * 384;
    pack_act<<<npairs / 256, 256>>>(x, x2, npairs);
    pack_wt<<<(2304 * 384) / 256, 256>>>(W_qkv, wt1, 2304);
    pack_wt<<<(768 * 384) / 256, 256>>>(W_proj, wt2, 768);
    // GEMM1: qkv = x @ W_qkv   [50176 x 2304]
    gemm_mma<<<392 * 18, 256, GEMM_SMEM>>>((const char*)x2, (const char*)wt1,
                                           qkv, nullptr, 2304, 18);
    // middle
    zero2<<<(256 * 2304 + 255) / 256, 256>>>(gram, 256 * 2304, nrm, 256 * 96);
    k_gram<<<256 * 8, 256>>>(qkv, gram, nrm);
    k_soft<<<256, 256>>>(gram, nrm, temp);
    k_apply<<<256 * 49, 256>>>(qkv, gram, mid2);
    // GEMM2: out = mid @ W_proj + b_proj   [50176 x 768]
    gemm_mma<<<392 * 6, 256, GEMM_SMEM>>>((const char*)mid2, (const char*)wt2,
                                          outp, b_proj, 768, 6);
}

// round 9
// speedup vs baseline: 2.8967x; 1.2299x over previous
#include <cuda_runtime.h>
#include <cuda_bf16.h>
#include <math.h>
#include <stdint.h>

// ---------------- problem constants ----------------
#define Bv 16
#define Sv 3136
#define Ev 768
#define Hv 16
#define Dv 48
#define NTOK (Bv * Sv)      // 50176
#define QKS 1536            // qk row stride (fp32)
#define LDK 4608            // bytes per packed row (768*3*2)
#define LDKU 1152           // u32 per packed row
#define NKCH 36             // K chunks of 64 bf16 (128 bytes)
#define NSTG 3
#define STG_BYTES 32768
#define GEMM_SMEM (NSTG * STG_BYTES)   // 98304

// ---------------- scratch (device globals; zero-initialized BSS) ----------
__device__ uint32_t g_x2[(size_t)(NTOK + 128) * LDKU]; // packed x (+pad rows)
__device__ float    g_qk[(size_t)NTOK * QKS];          // fp32 q,k
__device__ uint32_t g_wt1[(size_t)QKS * LDKU];         // W_qkv^T[0:1536] packed
__device__ uint32_t g_wv2[(size_t)Ev * LDKU];          // Wv rows packed (A layout)
__device__ float    g_gram[256 * 2304];                // 48x48 gram / attn
__device__ float    g_nrm[256 * 96];                   // squared norms
__device__ uint32_t g_Pt2[(size_t)Bv * Ev * LDKU];     // P_b^T packed (B layout)
__device__ float    g_Wb[(size_t)Bv * Ev * Ev];        // W_b = Wv @ P_b (fp32)
__device__ uint32_t g_wbT[(size_t)Bv * Ev * LDKU];     // W_b^T packed (B layout)

// ---------------- helpers ----------------
__device__ __forceinline__ uint32_t s2u(const void* p) {
    uint32_t a;
    asm("{ .reg .u64 t; cvta.to.shared.u64 t, %1; cvt.u32.u64 %0, t; }"
        : "=r"(a) : "l"(p));
    return a;
}
#define SWZ(o) ((o) ^ (((o) >> 3) & 0x70))

__device__ __forceinline__ void cpasync16(uint32_t s, const void* g) {
    asm volatile("cp.async.cg.shared.global [%0], [%1], 16;\n" :: "r"(s), "l"(g));
}
__device__ __forceinline__ void cp_commit() {
    asm volatile("cp.async.commit_group;\n");
}
template <int N> __device__ __forceinline__ void cp_wait() {
    asm volatile("cp.async.wait_group %0;\n" :: "n"(N));
}
__device__ __forceinline__ void ldm4(uint32_t& r0, uint32_t& r1, uint32_t& r2,
                                     uint32_t& r3, uint32_t a) {
    asm volatile("ldmatrix.sync.aligned.m8n8.x4.shared.b16 {%0,%1,%2,%3}, [%4];"
                 : "=r"(r0), "=r"(r1), "=r"(r2), "=r"(r3) : "r"(a));
}
__device__ __forceinline__ void mma16816(float* d, const uint32_t* a,
                                         const uint32_t* b) {
    asm volatile(
        "mma.sync.aligned.m16n8k16.row.col.f32.bf16.bf16.f32 "
        "{%0,%1,%2,%3}, {%4,%5,%6,%7}, {%8,%9}, {%0,%1,%2,%3};"
        : "+f"(d[0]), "+f"(d[1]), "+f"(d[2]), "+f"(d[3])
        : "r"(a[0]), "r"(a[1]), "r"(a[2]), "r"(a[3]), "r"(b[0]), "r"(b[1]));
}
__device__ __forceinline__ void split2(float x, uint32_t& h, uint32_t& l) {
    __nv_bfloat16 hb = __float2bfloat16(x);
    float rem = x - __bfloat162float(hb);
    __nv_bfloat16 lb = __float2bfloat16(rem);
    h = (uint32_t)__bfloat16_as_ushort(hb);
    l = (uint32_t)__bfloat16_as_ushort(lb);
}

// ---------------------------------------------------------------------------
// bf16 mma.sync GEMM (round-5/8 proven config) + batching + M-row store guard.
// C[m,n] = rowA_m . rowB_n over packed triplet K (36 chunks, LDK=4608).
// blockIdx.y = batch; per-batch byte strides for A/B, element stride for C.
// ---------------------------------------------------------------------------
__global__ __launch_bounds__(256, 2) void gemm_mma(
    const char* __restrict__ A, const char* __restrict__ B,
    float* __restrict__ C, const float* __restrict__ bias, int N, int NT,
    size_t aStride, size_t bStride, size_t cStride, int Mrows)
{
    extern __shared__ char sm[];
    const int tid  = threadIdx.x;
    const int wid  = tid >> 5, lane = tid & 31;
    const int wm   = wid & 3;
    const int wn   = wid >> 2;
    const int bm   = blockIdx.x / NT, bn = blockIdx.x % NT;
    const int bat  = blockIdx.y;
    const uint32_t smb = s2u(sm);

    const char* Ab = A + (size_t)bat * aStride + (size_t)bm * 128 * LDK;
    const char* Bb = B + (size_t)bat * bStride + (size_t)bn * 128 * LDK;

    const int ldr = tid >> 1;
    const int ldc = (tid & 1) * 64;

    auto loadch = [&](int sp, int ck) {
        uint32_t sa = smb + sp * STG_BYTES;
        uint32_t sb = sa + 16384;
        const char* a0 = Ab + ck * 128;
        const char* b0 = Bb + ck * 128;
        #pragma unroll
        for (int i = 0; i < 4; i++) {
            int cb = ldc + i * 16;
            cpasync16(sa + SWZ(ldr * 128 + cb), a0 + (size_t)ldr * LDK + cb);
            cpasync16(sb + SWZ(ldr * 128 + cb), b0 + (size_t)ldr * LDK + cb);
        }
        cp_commit();
    };

    float acc[2][8][4];
    #pragma unroll
    for (int m = 0; m < 2; m++)
        #pragma unroll
        for (int n = 0; n < 8; n++)
            #pragma unroll
            for (int p = 0; p < 4; p++) acc[m][n][p] = 0.f;

    loadch(0, 0);
    loadch(1, 1);

    const int a_row = (lane & 7) + ((lane >> 3) & 1) * 8;
    const int a_cb  = (lane >> 4) * 16;
    const int b_row = (lane & 7) + (lane >> 4) * 8;
    const int b_cb  = ((lane >> 3) & 1) * 16;

    uint32_t af[2][2][4], bf[2][8][2];

    auto ldfrag = [&](uint32_t sa, uint32_t sb, int ks, int buf) {
        #pragma unroll
        for (int mb = 0; mb < 2; mb++) {
            int r = wm * 32 + mb * 16 + a_row;
            ldm4(af[buf][mb][0], af[buf][mb][1], af[buf][mb][2], af[buf][mb][3],
                 sa + SWZ(r * 128 + ks * 32 + a_cb));
        }
        #pragma unroll
        for (int nb2 = 0; nb2 < 4; nb2++) {
            int r = wn * 64 + nb2 * 16 + b_row;
            ldm4(bf[buf][2 * nb2][0], bf[buf][2 * nb2][1],
                 bf[buf][2 * nb2 + 1][0], bf[buf][2 * nb2 + 1][1],
                 sb + SWZ(r * 128 + ks * 32 + b_cb));
        }
    };

    for (int k = 0; k < NKCH; k++) {
        cp_wait<1>();
        __syncthreads();

        int kp = k + 2;
        if (kp < NKCH) loadch(kp % NSTG, kp);
        else cp_commit();

        uint32_t sa = smb + (k % NSTG) * STG_BYTES;
        uint32_t sb = sa + 16384;

        ldfrag(sa, sb, 0, 0);
        #pragma unroll
        for (int ks = 0; ks < 4; ks++) {
            int c = ks & 1;
            if (ks < 3) ldfrag(sa, sb, ks + 1, c ^ 1);
            #pragma unroll
            for (int mb = 0; mb < 2; mb++)
                #pragma unroll
                for (int nb = 0; nb < 8; nb++)
                    mma16816(acc[mb][nb], af[c][mb], bf[c][nb]);
        }
    }

    // Epilogue with M-row guard (partial last tile in batched final GEMM)
    float* Cb = C + (size_t)bat * cStride
                + (size_t)(bm * 128 + wm * 32) * N + (size_t)bn * 128 + wn * 64;
    const int er = lane >> 2;
    const int ec = (lane & 3) * 2;
    const int rbase = bm * 128 + wm * 32;
    float bvs[8][2];
    #pragma unroll
    for (int nb = 0; nb < 8; nb++) {
        if (bias) {
            const float* bp = bias + (size_t)bn * 128 + wn * 64 + nb * 8 + ec;
            bvs[nb][0] = bp[0]; bvs[nb][1] = bp[1];
        } else { bvs[nb][0] = 0.f; bvs[nb][1] = 0.f; }
    }
    #pragma unroll
    for (int mb = 0; mb < 2; mb++) {
        int r0 = rbase + mb * 16 + er;
        bool w0 = r0 < Mrows, w1 = (r0 + 8) < Mrows;
        #pragma unroll
        for (int nb = 0; nb < 8; nb++) {
            int col = nb * 8 + ec;
            float2 v0 = {acc[mb][nb][0] + bvs[nb][0], acc[mb][nb][1] + bvs[nb][1]};
            float2 v1 = {acc[mb][nb][2] + bvs[nb][0], acc[mb][nb][3] + bvs[nb][1]};
            if (w0) *(float2*)(Cb + (size_t)(mb * 16 + er) * N + col) = v0;
            if (w1) *(float2*)(Cb + (size_t)(mb * 16 + er + 8) * N + col) = v1;
        }
    }
}

// ---------------------------------------------------------------------------
// Packing kernels.
// A layout per pair: [h0,h0,l0 | h1,h1,l1]; B layout: [h0,l0,h0 | h1,l1,h1]
// ---------------------------------------------------------------------------
__global__ void pack_act(const float* __restrict__ in, uint32_t* __restrict__ out,
                         int npairs)
{
    int t = blockIdx.x * 256 + threadIdx.x;
    if (t >= npairs) return;
    float2 xv = ((const float2*)in)[t];
    uint32_t h0, l0, h1, l1;
    split2(xv.x, h0, l0);
    split2(xv.y, h1, l1);
    out[3 * (size_t)t + 0] = h0 | (h0 << 16);
    out[3 * (size_t)t + 1] = l0 | (h1 << 16);
    out[3 * (size_t)t + 2] = h1 | (l1 << 16);
}

// transpose-pack of W columns -> B-layout rows. W: [768, stride] row-major;
// packs columns [0, ncols) into out rows. blockIdx.y = batch (Wb pack).
__global__ void pack_wt(const float* __restrict__ W, uint32_t* __restrict__ out,
                        int ncols, int stride, size_t wStride, size_t oStride)
{
    int t = blockIdx.x * 256 + threadIdx.x;
    if (t >= ncols * 384) return;
    const float* Wb = W + (size_t)blockIdx.y * wStride;
    uint32_t* ob = out + (size_t)blockIdx.y * oStride;
    int n = t / 384, kp = t % 384;
    float x0 = Wb[(size_t)(2 * kp) * stride + n];
    float x1 = Wb[(size_t)(2 * kp + 1) * stride + n];
    uint32_t h0, l0, h1, l1;
    split2(x0, h0, l0);
    split2(x1, h1, l1);
    uint32_t* o = ob + (size_t)n * LDKU + 3 * kp;
    o[0] = h0 | (l0 << 16);
    o[1] = h0 | (h1 << 16);
    o[2] = l1 | (h1 << 16);
}

// pack Wv rows (A layout): Wv = W_qkv[:, 1536:2304] (contiguous per row)
__global__ void pack_wv(const float* __restrict__ Wqkv, uint32_t* __restrict__ out)
{
    int t = blockIdx.x * 256 + threadIdx.x;   // 768*384 pairs
    if (t >= Ev * 384) return;
    int e = t / 384, c = t % 384;
    float x0 = Wqkv[(size_t)e * 2304 + 1536 + 2 * c];
    float x1 = Wqkv[(size_t)e * 2304 + 1536 + 2 * c + 1];
    uint32_t h0, l0, h1, l1;
    split2(x0, h0, l0);
    split2(x1, h1, l1);
    uint32_t* o = out + (size_t)e * LDKU + 3 * c;
    o[0] = h0 | (h0 << 16);
    o[1] = l0 | (h1 << 16);
    o[2] = h1 | (l1 << 16);
}

__global__ void zero2(float* a, int na, float* b, int nb)
{
    int t = blockIdx.x * 256 + threadIdx.x;
    if (t < na) a[t] = 0.f;
    if (t < nb) b[t] = 0.f;
}

// ---------------------------------------------------------------------------
// Gram + norms (round-6 proven, stride 1536)
// ---------------------------------------------------------------------------
#define GCH 56
__global__ __launch_bounds__(256) void k_gram(
    const float* __restrict__ qk, float* __restrict__ gram, float* __restrict__ nrm)
{
    __shared__ float qs[Dv][GCH + 1];
    __shared__ float ks[Dv][GCH + 1];
    const int bh = blockIdx.x >> 3, ck = blockIdx.x & 7;
    const int b = bh >> 4, h = bh & 15;
    const int tid = threadIdx.x;
    const int tx = tid & 15, ty = tid >> 4;
    const size_t base = ((size_t)b * Sv + ck * 392) * QKS + (size_t)h * Dv;

    float acc[3][3];
    #pragma unroll
    for (int r = 0; r < 3; r++)
        #pragma unroll
        for (int c = 0; c < 3; c++) acc[r][c] = 0.f;
    float na = 0.f;

    for (int s0 = 0; s0 < 392; s0 += GCH) {
        for (int idx = tid; idx < Dv * GCH; idx += 256) {
            int i = idx % Dv, sl = idx / Dv;
            size_t g = base + (size_t)(s0 + sl) * QKS + i;
            qs[i][sl] = qk[g];
            ks[i][sl] = qk[g + Ev];
        }
        __syncthreads();
        #pragma unroll 4
        for (int sl = 0; sl < GCH; sl++) {
            float qv[3], kv[3];
            #pragma unroll
            for (int r = 0; r < 3; r++) qv[r] = qs[3 * ty + r][sl];
            #pragma unroll
            for (int c = 0; c < 3; c++) kv[c] = ks[3 * tx + c][sl];
            #pragma unroll
            for (int r = 0; r < 3; r++)
                #pragma unroll
                for (int c = 0; c < 3; c++)
                    acc[r][c] = fmaf(qv[r], kv[c], acc[r][c]);
        }
        if (tid < 2 * Dv) {
            const float* row = (tid < Dv) ? qs[tid] : ks[tid - Dv];
            float a = 0.f;
            #pragma unroll 8
            for (int sl = 0; sl < GCH; sl++) a = fmaf(row[sl], row[sl], a);
            na += a;
        }
        __syncthreads();
    }
    #pragma unroll
    for (int r = 0; r < 3; r++)
        #pragma unroll
        for (int c = 0; c < 3; c++)
            atomicAdd(gram + (size_t)bh * 2304 + (3 * ty + r) * Dv + 3 * tx + c,
                      acc[r][c]);
    if (tid < 96) atomicAdd(nrm + (size_t)bh * 96 + tid, na);
}

__global__ __launch_bounds__(256) void k_soft(
    float* __restrict__ gram, const float* __restrict__ nrm2,
    const float* __restrict__ temp)
{
    __shared__ float Gs[Dv][Dv];
    __shared__ float nr[96];
    const int bh = blockIdx.x;
    const int h = bh & 15;
    const int tid = threadIdx.x;
    for (int idx = tid; idx < 2304; idx += 256)
        Gs[idx / Dv][idx % Dv] = gram[(size_t)bh * 2304 + idx];
    if (tid < 96) nr[tid] = fmaxf(sqrtf(nrm2[(size_t)bh * 96 + tid]), 1e-12f);
    __syncthreads();
    const float T = temp[h];
    const int warp = tid >> 5, lane = tid & 31;
    for (int i = warp; i < Dv; i += 8) {
        float inq = T / nr[i];
        int j0 = lane, j1 = lane + 32;
        float v0 = Gs[i][j0] * inq / nr[Dv + j0];
        float v1 = (j1 < Dv) ? Gs[i][j1] * inq / nr[Dv + j1] : -INFINITY;
        float m = fmaxf(v0, v1);
        #pragma unroll
        for (int o = 16; o; o >>= 1) m = fmaxf(m, __shfl_xor_sync(~0u, m, o));
        float e0 = expf(v0 - m);
        float e1 = (j1 < Dv) ? expf(v1 - m) : 0.f;
        float ss = e0 + e1;
        #pragma unroll
        for (int o = 16; o; o >>= 1) ss += __shfl_xor_sync(~0u, ss, o);
        float inv = 1.f / ss;
        gram[(size_t)bh * 2304 + i * Dv + j0] = e0 * inv;
        if (j1 < Dv) gram[(size_t)bh * 2304 + i * Dv + j1] = e1 * inv;
    }
}

// ---------------------------------------------------------------------------
// Fold: P_b^T[n, (h,j)] = sum_i attn_bh[i,j] * W_proj[(h,i), n], written
// directly as packed B-layout triplets. grid = (6 n-blocks, 256 bh).
// ---------------------------------------------------------------------------
__global__ __launch_bounds__(256) void k_fold(
    const float* __restrict__ attn, const float* __restrict__ Wp,
    uint32_t* __restrict__ Pt2)
{
    __shared__ float As[Dv][Dv + 1];
    __shared__ float Ws[Dv][128];
    const int nb = blockIdx.x;
    const int bh = blockIdx.y;
    const int b = bh >> 4, h = bh & 15;
    const int tid = threadIdx.x;
    const int tx = tid & 127;      // n within block
    const int tz = tid >> 7;       // j half (24 each)

    for (int idx = tid; idx < Dv * Dv; idx += 256)
        As[idx / Dv][idx % Dv] = attn[(size_t)bh * 2304 + idx];
    for (int idx = tid; idx < Dv * 128; idx += 256) {
        int i = idx >> 7, c = idx & 127;
        Ws[i][c] = Wp[(size_t)(h * Dv + i) * Ev + nb * 128 + c];
    }
    __syncthreads();

    float acc[24];
    #pragma unroll
    for (int j = 0; j < 24; j++) acc[j] = 0.f;
    #pragma unroll 4
    for (int i = 0; i < Dv; i++) {
        float a = Ws[i][tx];
        #pragma unroll
        for (int j = 0; j < 24; j++)
            acc[j] = fmaf(As[i][tz * 24 + j], a, acc[j]);
    }

    int n = nb * 128 + tx;
    uint32_t* ob = Pt2 + (size_t)b * Ev * LDKU + (size_t)n * LDKU;
    #pragma unroll
    for (int t = 0; t < 12; t++) {
        uint32_t h0, l0, h1, l1;
        split2(acc[2 * t], h0, l0);
        split2(acc[2 * t + 1], h1, l1);
        uint32_t* o = ob + 3 * (h * 24 + tz * 12 + t);
        o[0] = h0 | (l0 << 16);
        o[1] = h0 | (h1 << 16);
        o[2] = l1 | (h1 << 16);
    }
}

// ---------------------------------------------------------------------------
// Launch
// ---------------------------------------------------------------------------
extern "C" void kernel_launch(void* const* d_in, const int* in_sizes, int n_in,
                              void* d_out, int out_size)
{
    const float* x      = (const float*)d_in[0];
    const float* W_qkv  = (const float*)d_in[1];
    const float* W_proj = (const float*)d_in[2];
    const float* b_proj = (const float*)d_in[3];
    const float* temp   = (const float*)d_in[4];
    float* outp = (float*)d_out;

    uint32_t *x2, *wt1, *wv2, *Pt2, *wbT;
    float *qk, *gram, *nrm, *Wb;
    cudaGetSymbolAddress((void**)&x2, g_x2);
    cudaGetSymbolAddress((void**)&wt1, g_wt1);
    cudaGetSymbolAddress((void**)&wv2, g_wv2);
    cudaGetSymbolAddress((void**)&Pt2, g_Pt2);
    cudaGetSymbolAddress((void**)&wbT, g_wbT);
    cudaGetSymbolAddress((void**)&qk, g_qk);
    cudaGetSymbolAddress((void**)&gram, g_gram);
    cudaGetSymbolAddress((void**)&nrm, g_nrm);
    cudaGetSymbolAddress((void**)&Wb, g_Wb);

    cudaFuncSetAttribute(gemm_mma, cudaFuncAttributeMaxDynamicSharedMemorySize,
                         GEMM_SMEM);

    // packing
    int npairs = NTOK * 384;
    pack_act<<<npairs / 256, 256>>>(x, x2, npairs);
    pack_wt<<<(QKS * 384) / 256, 256>>>(W_qkv, wt1, QKS, 2304, 0, 0);
    pack_wv<<<(Ev * 384) / 256, 256>>>(W_qkv, wv2);

    // GEMM1: qk = x @ W_qkv[:, 0:1536]
    {
        dim3 grid(392 * 12, 1);
        gemm_mma<<<grid, 256, GEMM_SMEM>>>((const char*)x2, (const char*)wt1,
                                           qk, nullptr, QKS, 12, 0, 0, 0,
                                           1 << 30);
    }
    // gram + softmax
    zero2<<<(256 * 2304 + 255) / 256, 256>>>(gram, 256 * 2304, nrm, 256 * 96);
    k_gram<<<256 * 8, 256>>>(qk, gram, nrm);
    k_soft<<<256, 256>>>(gram, nrm, temp);

    // fold: P_b^T packed
    {
        dim3 grid(6, 256);
        k_fold<<<grid, 256>>>(gram, W_proj, Pt2);
    }
    // W_b = Wv @ P_b  (batched 768x768, K=768)
    {
        dim3 grid(36, 16);
        gemm_mma<<<grid, 256, GEMM_SMEM>>>((const char*)wv2, (const char*)Pt2,
                                           Wb, nullptr, Ev, 6,
                                           0, (size_t)Ev * LDKU * 4,
                                           (size_t)Ev * Ev, 1 << 30);
    }
    // pack W_b^T (batched)
    {
        dim3 grid((Ev * 384) / 256, 16);
        pack_wt<<<grid, 256>>>(Wb, wbT, Ev, Ev,
                               (size_t)Ev * Ev, (size_t)Ev * LDKU);
    }
    // final: out_b = X_b @ W_b + b_proj  (batched, M=3136 with guard)
    {
        dim3 grid(25 * 6, 16);
        gemm_mma<<<grid, 256, GEMM_SMEM>>>((const char*)x2, (const char*)wbT,
                                           outp, b_proj, Ev, 6,
                                           (size_t)Sv * LDK,
                                           (size_t)Ev * LDKU * 4,
                                           (size_t)Sv * Ev, Sv);
    }
}

// round 10
// speedup vs baseline: 3.2079x; 1.1074x over previous
#include <cuda_runtime.h>
#include <cuda_bf16.h>
#include <math.h>
#include <stdint.h>

// ---------------- problem constants ----------------
#define Bv 16
#define Sv 3136
#define Ev 768
#define Hv 16
#define Dv 48
#define NTOK (Bv * Sv)      // 50176
#define LDK 4608            // bytes per packed row, K=768 triplet (2304 bf16)
#define LDKU 1152           // u32 per packed row (K=768 triplet)
#define LDK2 18816          // bytes per packed row, K=3136 triplet (9408 bf16)
#define LDKU2 4704          // u32
#define NSTG 3
#define STG_BYTES 32768
#define GEMM_SMEM (NSTG * STG_BYTES)   // 98304

// ---------------- scratch (device globals) ----------------
__device__ uint32_t g_x2[(size_t)(NTOK + 128) * LDKU]; // packed x rows (A layout)
__device__ uint32_t g_xtA[(size_t)Bv * Ev * LDKU2];    // X^T packed, A layout
__device__ uint32_t g_xtB[(size_t)Bv * Ev * LDKU2];    // X^T packed, B layout
__device__ float    g_C[(size_t)Bv * Ev * Ev];         // C = X^T X (upper tiles)
__device__ uint32_t g_Cp[(size_t)Bv * Ev * LDKU];      // C packed (A layout)
__device__ float    g_V2[(size_t)Bv * Ev * 1536];      // C @ [Wq|Wk]
__device__ uint32_t g_wt1[(size_t)1536 * LDKU];        // [Wq|Wk]^T packed (B)
__device__ uint32_t g_wv2[(size_t)Ev * LDKU];          // Wv rows packed (A)
__device__ float    g_gram[256 * 2304];                // 48x48 gram / attn
__device__ float    g_nrm[256 * 96];                   // squared norms
__device__ uint32_t g_Pt2[(size_t)Bv * Ev * LDKU];     // P_b^T packed (B)
__device__ float    g_Wb[(size_t)Bv * Ev * Ev];        // W_b = Wv @ P_b
__device__ uint32_t g_wbT[(size_t)Bv * Ev * LDKU];     // W_b^T packed (B)

// ---------------- helpers ----------------
__device__ __forceinline__ uint32_t s2u(const void* p) {
    uint32_t a;
    asm("{ .reg .u64 t; cvta.to.shared.u64 t, %1; cvt.u32.u64 %0, t; }"
        : "=r"(a) : "l"(p));
    return a;
}
#define SWZ(o) ((o) ^ (((o) >> 3) & 0x70))

__device__ __forceinline__ void cpasync16(uint32_t s, const void* g) {
    asm volatile("cp.async.cg.shared.global [%0], [%1], 16;\n" :: "r"(s), "l"(g));
}
__device__ __forceinline__ void cp_commit() {
    asm volatile("cp.async.commit_group;\n");
}
template <int N> __device__ __forceinline__ void cp_wait() {
    asm volatile("cp.async.wait_group %0;\n" :: "n"(N));
}
__device__ __forceinline__ void ldm4(uint32_t& r0, uint32_t& r1, uint32_t& r2,
                                     uint32_t& r3, uint32_t a) {
    asm volatile("ldmatrix.sync.aligned.m8n8.x4.shared.b16 {%0,%1,%2,%3}, [%4];"
                 : "=r"(r0), "=r"(r1), "=r"(r2), "=r"(r3) : "r"(a));
}
__device__ __forceinline__ void mma16816(float* d, const uint32_t* a,
                                         const uint32_t* b) {
    asm volatile(
        "mma.sync.aligned.m16n8k16.row.col.f32.bf16.bf16.f32 "
        "{%0,%1,%2,%3}, {%4,%5,%6,%7}, {%8,%9}, {%0,%1,%2,%3};"
        : "+f"(d[0]), "+f"(d[1]), "+f"(d[2]), "+f"(d[3])
        : "r"(a[0]), "r"(a[1]), "r"(a[2]), "r"(a[3]), "r"(b[0]), "r"(b[1]));
}
__device__ __forceinline__ void split2(float x, uint32_t& h, uint32_t& l) {
    __nv_bfloat16 hb = __float2bfloat16(x);
    float rem = x - __bfloat162float(hb);
    __nv_bfloat16 lb = __float2bfloat16(rem);
    h = (uint32_t)__bfloat16_as_ushort(hb);
    l = (uint32_t)__bfloat16_as_ushort(lb);
}

// ---------------------------------------------------------------------------
// bf16 mma.sync GEMM (proven config) with runtime K length, batching,
// M-row store guard, and optional triangular 6x6 tile decode (tri=1).
// ---------------------------------------------------------------------------
__global__ __launch_bounds__(256, 2) void gemm_mma(
    const char* __restrict__ A, const char* __restrict__ B,
    float* __restrict__ C, const float* __restrict__ bias, int N, int NT,
    size_t aStride, size_t bStride, size_t cStride, int Mrows,
    int kRowBytes, int nkch, int tri)
{
    extern __shared__ char sm[];
    const int tid  = threadIdx.x;
    const int wid  = tid >> 5, lane = tid & 31;
    const int wm   = wid & 3;
    const int wn   = wid >> 2;
    const int bat  = blockIdx.y;
    int bm, bn;
    if (tri) {
        int t = blockIdx.x, r = 0, rl = 6;
        while (t >= rl) { t -= rl; rl--; r++; }
        bm = r; bn = r + t;
    } else {
        bm = blockIdx.x / NT; bn = blockIdx.x % NT;
    }
    const uint32_t smb = s2u(sm);

    const char* Ab = A + (size_t)bat * aStride + (size_t)bm * 128 * kRowBytes;
    const char* Bb = B + (size_t)bat * bStride + (size_t)bn * 128 * kRowBytes;

    const int ldr = tid >> 1;
    const int ldc = (tid & 1) * 64;

    auto loadch = [&](int sp, int ck) {
        uint32_t sa = smb + sp * STG_BYTES;
        uint32_t sb = sa + 16384;
        const char* a0 = Ab + ck * 128;
        const char* b0 = Bb + ck * 128;
        #pragma unroll
        for (int i = 0; i < 4; i++) {
            int cb = ldc + i * 16;
            cpasync16(sa + SWZ(ldr * 128 + cb), a0 + (size_t)ldr * kRowBytes + cb);
            cpasync16(sb + SWZ(ldr * 128 + cb), b0 + (size_t)ldr * kRowBytes + cb);
        }
        cp_commit();
    };

    float acc[2][8][4];
    #pragma unroll
    for (int m = 0; m < 2; m++)
        #pragma unroll
        for (int n = 0; n < 8; n++)
            #pragma unroll
            for (int p = 0; p < 4; p++) acc[m][n][p] = 0.f;

    loadch(0, 0);
    loadch(1, 1);

    const int a_row = (lane & 7) + ((lane >> 3) & 1) * 8;
    const int a_cb  = (lane >> 4) * 16;
    const int b_row = (lane & 7) + (lane >> 4) * 8;
    const int b_cb  = ((lane >> 3) & 1) * 16;

    uint32_t af[2][2][4], bf[2][8][2];

    auto ldfrag = [&](uint32_t sa, uint32_t sb, int ks, int buf) {
        #pragma unroll
        for (int mb = 0; mb < 2; mb++) {
            int r = wm * 32 + mb * 16 + a_row;
            ldm4(af[buf][mb][0], af[buf][mb][1], af[buf][mb][2], af[buf][mb][3],
                 sa + SWZ(r * 128 + ks * 32 + a_cb));
        }
        #pragma unroll
        for (int nb2 = 0; nb2 < 4; nb2++) {
            int r = wn * 64 + nb2 * 16 + b_row;
            ldm4(bf[buf][2 * nb2][0], bf[buf][2 * nb2][1],
                 bf[buf][2 * nb2 + 1][0], bf[buf][2 * nb2 + 1][1],
                 sb + SWZ(r * 128 + ks * 32 + b_cb));
        }
    };

    for (int k = 0; k < nkch; k++) {
        cp_wait<1>();
        __syncthreads();

        int kp = k + 2;
        if (kp < nkch) loadch(kp % NSTG, kp);
        else cp_commit();

        uint32_t sa = smb + (k % NSTG) * STG_BYTES;
        uint32_t sb = sa + 16384;

        ldfrag(sa, sb, 0, 0);
        #pragma unroll
        for (int ks = 0; ks < 4; ks++) {
            int c = ks & 1;
            if (ks < 3) ldfrag(sa, sb, ks + 1, c ^ 1);
            #pragma unroll
            for (int mb = 0; mb < 2; mb++)
                #pragma unroll
                for (int nb = 0; nb < 8; nb++)
                    mma16816(acc[mb][nb], af[c][mb], bf[c][nb]);
        }
    }

    float* Cb = C + (size_t)bat * cStride
                + (size_t)(bm * 128 + wm * 32) * N + (size_t)bn * 128 + wn * 64;
    const int er = lane >> 2;
    const int ec = (lane & 3) * 2;
    const int rbase = bm * 128 + wm * 32;
    float bvs[8][2];
    #pragma unroll
    for (int nb = 0; nb < 8; nb++) {
        if (bias) {
            const float* bp = bias + (size_t)bn * 128 + wn * 64 + nb * 8 + ec;
            bvs[nb][0] = bp[0]; bvs[nb][1] = bp[1];
        } else { bvs[nb][0] = 0.f; bvs[nb][1] = 0.f; }
    }
    #pragma unroll
    for (int mb = 0; mb < 2; mb++) {
        int r0 = rbase + mb * 16 + er;
        bool w0 = r0 < Mrows, w1 = (r0 + 8) < Mrows;
        #pragma unroll
        for (int nb = 0; nb < 8; nb++) {
            int col = nb * 8 + ec;
            float2 v0 = {acc[mb][nb][0] + bvs[nb][0], acc[mb][nb][1] + bvs[nb][1]};
            float2 v1 = {acc[mb][nb][2] + bvs[nb][0], acc[mb][nb][3] + bvs[nb][1]};
            if (w0) *(float2*)(Cb + (size_t)(mb * 16 + er) * N + col) = v0;
            if (w1) *(float2*)(Cb + (size_t)(mb * 16 + er + 8) * N + col) = v1;
        }
    }
}

// ---------------------------------------------------------------------------
// Packing kernels.
// A layout per pair: [h0,h0,l0 | h1,h1,l1]; B layout: [h0,l0,h0 | h1,l1,h1]
// ---------------------------------------------------------------------------
__global__ void pack_act(const float* __restrict__ in, uint32_t* __restrict__ out,
                         int npairs)
{
    int t = blockIdx.x * 256 + threadIdx.x;
    if (t >= npairs) return;
    float2 xv = ((const float2*)in)[t];
    uint32_t h0, l0, h1, l1;
    split2(xv.x, h0, l0);
    split2(xv.y, h1, l1);
    out[3 * (size_t)t + 0] = h0 | (h0 << 16);
    out[3 * (size_t)t + 1] = l0 | (h1 << 16);
    out[3 * (size_t)t + 2] = h1 | (l1 << 16);
}

// transpose-pack X^T into BOTH layouts: 64x64 smem tile per block.
// grid = (12 e-tiles, 49 s-tiles, 16 batches)
__global__ __launch_bounds__(256) void pack_xt(
    const float* __restrict__ x, uint32_t* __restrict__ outA,
    uint32_t* __restrict__ outB)
{
    __shared__ float ts[64][65];
    const int e0 = blockIdx.x * 64, s0 = blockIdx.y * 64, b = blockIdx.z;
    const int tid = threadIdx.x;
    #pragma unroll
    for (int i = 0; i < 16; i++) {
        int idx = tid + i * 256;
        int sl = idx >> 6, el = idx & 63;
        ts[sl][el] = x[((size_t)b * Sv + s0 + sl) * Ev + e0 + el];
    }
    __syncthreads();
    #pragma unroll
    for (int i = 0; i < 8; i++) {
        int item = tid + i * 256;
        int el = item >> 5, sp = item & 31;
        float v0 = ts[2 * sp][el], v1 = ts[2 * sp + 1][el];
        uint32_t h0, l0, h1, l1;
        split2(v0, h0, l0);
        split2(v1, h1, l1);
        size_t rb = ((size_t)b * Ev + e0 + el) * LDKU2 + 3 * (blockIdx.y * 32 + sp);
        outA[rb + 0] = h0 | (h0 << 16);
        outA[rb + 1] = l0 | (h1 << 16);
        outA[rb + 2] = h1 | (l1 << 16);
        outB[rb + 0] = h0 | (l0 << 16);
        outB[rb + 1] = h0 | (h1 << 16);
        outB[rb + 2] = l1 | (h1 << 16);
    }
}

// transpose-pack of W columns -> B-layout rows (batched via blockIdx.y)
__global__ void pack_wt(const float* __restrict__ W, uint32_t* __restrict__ out,
                        int ncols, int stride, size_t wStride, size_t oStride)
{
    int t = blockIdx.x * 256 + threadIdx.x;
    if (t >= ncols * 384) return;
    const float* Wb = W + (size_t)blockIdx.y * wStride;
    uint32_t* ob = out + (size_t)blockIdx.y * oStride;
    int n = t / 384, kp = t % 384;
    float x0 = Wb[(size_t)(2 * kp) * stride + n];
    float x1 = Wb[(size_t)(2 * kp + 1) * stride + n];
    uint32_t h0, l0, h1, l1;
    split2(x0, h0, l0);
    split2(x1, h1, l1);
    uint32_t* o = ob + (size_t)n * LDKU + 3 * kp;
    o[0] = h0 | (l0 << 16);
    o[1] = h0 | (h1 << 16);
    o[2] = l1 | (h1 << 16);
}

// pack Wv rows (A layout): Wv = W_qkv[:, 1536:2304]
__global__ void pack_wv(const float* __restrict__ Wqkv, uint32_t* __restrict__ out)
{
    int t = blockIdx.x * 256 + threadIdx.x;
    if (t >= Ev * 384) return;
    int e = t / 384, c = t % 384;
    float x0 = Wqkv[(size_t)e * 2304 + 1536 + 2 * c];
    float x1 = Wqkv[(size_t)e * 2304 + 1536 + 2 * c + 1];
    uint32_t h0, l0, h1, l1;
    split2(x0, h0, l0);
    split2(x1, h1, l1);
    uint32_t* o = out + (size_t)e * LDKU + 3 * c;
    o[0] = h0 | (h0 << 16);
    o[1] = l0 | (h1 << 16);
    o[2] = h1 | (l1 << 16);
}

// pack C rows into A layout, mirroring lower tiles from upper storage.
// grid = (1152, 16); t -> (e1, pair)
__global__ void pack_ct(const float* __restrict__ C, uint32_t* __restrict__ out)
{
    int t = blockIdx.x * 256 + threadIdx.x;   // < 768*384
    const float* Cb = C + (size_t)blockIdx.y * Ev * Ev;
    uint32_t* ob = out + (size_t)blockIdx.y * Ev * LDKU;
    int e1 = t / 384, p = t % 384;
    int e2a = 2 * p, e2b = 2 * p + 1;
    int t1 = e1 >> 7;
    float x0 = (t1 <= (e2a >> 7)) ? Cb[(size_t)e1 * Ev + e2a]
                                  : Cb[(size_t)e2a * Ev + e1];
    float x1 = (t1 <= (e2b >> 7)) ? Cb[(size_t)e1 * Ev + e2b]
                                  : Cb[(size_t)e2b * Ev + e1];
    uint32_t h0, l0, h1, l1;
    split2(x0, h0, l0);
    split2(x1, h1, l1);
    uint32_t* o = ob + (size_t)e1 * LDKU + 3 * p;
    o[0] = h0 | (h0 << 16);
    o[1] = l0 | (h1 << 16);
    o[2] = h1 | (l1 << 16);
}

// ---------------------------------------------------------------------------
// G + norms from weights and V2 = C @ [Wq|Wk].
// G_bh[i][j] = sum_e Wq[e,h48+i] * V2[e, 768+h48+j]
// nq2[i] = sum_e Wq[e,h48+i] * V2[e, h48+i]; nk2[j] = sum_e Wk[e,.]*V2[e,768+.]
// ---------------------------------------------------------------------------
#define CH2 48
__global__ __launch_bounds__(256) void k_gram2(
    const float* __restrict__ Wqkv, const float* __restrict__ V2,
    float* __restrict__ gram, float* __restrict__ nrm)
{
    __shared__ float Wqs[Dv][CH2 + 1];
    __shared__ float Wks[Dv][CH2 + 1];
    __shared__ float Tqs[Dv][CH2 + 1];
    __shared__ float Us[Dv][CH2 + 1];
    const int bh = blockIdx.x;
    const int b = bh >> 4, h = bh & 15;
    const int tid = threadIdx.x;
    const int tx = tid & 15, ty = tid >> 4;

    float acc[3][3];
    #pragma unroll
    for (int r = 0; r < 3; r++)
        #pragma unroll
        for (int c = 0; c < 3; c++) acc[r][c] = 0.f;
    float na = 0.f;

    for (int e0 = 0; e0 < Ev; e0 += CH2) {
        for (int idx = tid; idx < Dv * CH2; idx += 256) {
            int i = idx % Dv, el = idx / Dv;
            int e = e0 + el;
            const float* wrow = Wqkv + (size_t)e * 2304 + h * Dv;
            const float* vrow = V2 + ((size_t)b * Ev + e) * 1536 + h * Dv;
            Wqs[i][el] = wrow[i];
            Wks[i][el] = wrow[768 + i];
            Tqs[i][el] = vrow[i];
            Us[i][el]  = vrow[768 + i];
        }
        __syncthreads();
        #pragma unroll 4
        for (int el = 0; el < CH2; el++) {
            float qv[3], uv[3];
            #pragma unroll
            for (int r = 0; r < 3; r++) qv[r] = Wqs[3 * ty + r][el];
            #pragma unroll
            for (int c = 0; c < 3; c++) uv[c] = Us[3 * tx + c][el];
            #pragma unroll
            for (int r = 0; r < 3; r++)
                #pragma unroll
                for (int c = 0; c < 3; c++)
                    acc[r][c] = fmaf(qv[r], uv[c], acc[r][c]);
        }
        if (tid < 2 * Dv) {
            float a = 0.f;
            if (tid < Dv) {
                #pragma unroll 8
                for (int el = 0; el < CH2; el++)
                    a = fmaf(Wqs[tid][el], Tqs[tid][el], a);
            } else {
                int j = tid - Dv;
                #pragma unroll 8
                for (int el = 0; el < CH2; el++)
                    a = fmaf(Wks[j][el], Us[j][el], a);
            }
            na += a;
        }
        __syncthreads();
    }
    #pragma unroll
    for (int r = 0; r < 3; r++)
        #pragma unroll
        for (int c = 0; c < 3; c++)
            gram[(size_t)bh * 2304 + (3 * ty + r) * Dv + 3 * tx + c] = acc[r][c];
    if (tid < 96) nrm[(size_t)bh * 96 + tid] = na;
}

__global__ __launch_bounds__(256) void k_soft(
    float* __restrict__ gram, const float* __restrict__ nrm2,
    const float* __restrict__ temp)
{
    __shared__ float Gs[Dv][Dv];
    __shared__ float nr[96];
    const int bh = blockIdx.x;
    const int h = bh & 15;
    const int tid = threadIdx.x;
    for (int idx = tid; idx < 2304; idx += 256)
        Gs[idx / Dv][idx % Dv] = gram[(size_t)bh * 2304 + idx];
    if (tid < 96) nr[tid] = fmaxf(sqrtf(nrm2[(size_t)bh * 96 + tid]), 1e-12f);
    __syncthreads();
    const float T = temp[h];
    const int warp = tid >> 5, lane = tid & 31;
    for (int i = warp; i < Dv; i += 8) {
        float inq = T / nr[i];
        int j0 = lane, j1 = lane + 32;
        float v0 = Gs[i][j0] * inq / nr[Dv + j0];
        float v1 = (j1 < Dv) ? Gs[i][j1] * inq / nr[Dv + j1] : -INFINITY;
        float m = fmaxf(v0, v1);
        #pragma unroll
        for (int o = 16; o; o >>= 1) m = fmaxf(m, __shfl_xor_sync(~0u, m, o));
        float e0 = expf(v0 - m);
        float e1 = (j1 < Dv) ? expf(v1 - m) : 0.f;
        float ss = e0 + e1;
        #pragma unroll
        for (int o = 16; o; o >>= 1) ss += __shfl_xor_sync(~0u, ss, o);
        float inv = 1.f / ss;
        gram[(size_t)bh * 2304 + i * Dv + j0] = e0 * inv;
        if (j1 < Dv) gram[(size_t)bh * 2304 + i * Dv + j1] = e1 * inv;
    }
}

// Fold: P_b^T[n,(h,j)] = sum_i attn_bh[i,j] * W_proj[(h,i), n] (packed B)
__global__ __launch_bounds__(256) void k_fold(
    const float* __restrict__ attn, const float* __restrict__ Wp,
    uint32_t* __restrict__ Pt2)
{
    __shared__ float As[Dv][Dv + 1];
    __shared__ float Ws[Dv][128];
    const int nb = blockIdx.x;
    const int bh = blockIdx.y;
    const int b = bh >> 4, h = bh & 15;
    const int tid = threadIdx.x;
    const int tx = tid & 127;
    const int tz = tid >> 7;

    for (int idx = tid; idx < Dv * Dv; idx += 256)
        As[idx / Dv][idx % Dv] = attn[(size_t)bh * 2304 + idx];
    for (int idx = tid; idx < Dv * 128; idx += 256) {
        int i = idx >> 7, c = idx & 127;
        Ws[i][c] = Wp[(size_t)(h * Dv + i) * Ev + nb * 128 + c];
    }
    __syncthreads();

    float acc[24];
    #pragma unroll
    for (int j = 0; j < 24; j++) acc[j] = 0.f;
    #pragma unroll 4
    for (int i = 0; i < Dv; i++) {
        float a = Ws[i][tx];
        #pragma unroll
        for (int j = 0; j < 24; j++)
            acc[j] = fmaf(As[i][tz * 24 + j], a, acc[j]);
    }

    int n = nb * 128 + tx;
    uint32_t* ob = Pt2 + (size_t)b * Ev * LDKU + (size_t)n * LDKU;
    #pragma unroll
    for (int t = 0; t < 12; t++) {
        uint32_t h0, l0, h1, l1;
        split2(acc[2 * t], h0, l0);
        split2(acc[2 * t + 1], h1, l1);
        uint32_t* o = ob + 3 * (h * 24 + tz * 12 + t);
        o[0] = h0 | (l0 << 16);
        o[1] = h0 | (h1 << 16);
        o[2] = l1 | (h1 << 16);
    }
}

// ---------------------------------------------------------------------------
// Launch
// ---------------------------------------------------------------------------
extern "C" void kernel_launch(void* const* d_in, const int* in_sizes, int n_in,
                              void* d_out, int out_size)
{
    const float* x      = (const float*)d_in[0];
    const float* W_qkv  = (const float*)d_in[1];
    const float* W_proj = (const float*)d_in[2];
    const float* b_proj = (const float*)d_in[3];
    const float* temp   = (const float*)d_in[4];
    float* outp = (float*)d_out;

    uint32_t *x2, *xtA, *xtB, *Cp, *wt1, *wv2, *Pt2, *wbT;
    float *Cbuf, *V2, *gram, *nrm, *Wb;
    cudaGetSymbolAddress((void**)&x2, g_x2);
    cudaGetSymbolAddress((void**)&xtA, g_xtA);
    cudaGetSymbolAddress((void**)&xtB, g_xtB);
    cudaGetSymbolAddress((void**)&Cp, g_Cp);
    cudaGetSymbolAddress((void**)&wt1, g_wt1);
    cudaGetSymbolAddress((void**)&wv2, g_wv2);
    cudaGetSymbolAddress((void**)&Pt2, g_Pt2);
    cudaGetSymbolAddress((void**)&wbT, g_wbT);
    cudaGetSymbolAddress((void**)&Cbuf, g_C);
    cudaGetSymbolAddress((void**)&V2, g_V2);
    cudaGetSymbolAddress((void**)&gram, g_gram);
    cudaGetSymbolAddress((void**)&nrm, g_nrm);
    cudaGetSymbolAddress((void**)&Wb, g_Wb);

    cudaFuncSetAttribute(gemm_mma, cudaFuncAttributeMaxDynamicSharedMemorySize,
                         GEMM_SMEM);

    // packing
    int npairs = NTOK * 384;
    pack_act<<<npairs / 256, 256>>>(x, x2, npairs);
    {
        dim3 grid(12, 49, 16);
        pack_xt<<<grid, 256>>>(x, xtA, xtB);
    }
    pack_wt<<<(1536 * 384) / 256, 256>>>(W_qkv, wt1, 1536, 2304, 0, 0);
    pack_wv<<<(Ev * 384) / 256, 256>>>(W_qkv, wv2);

    // C = X^T X  (upper tiles only; batched; K=3136 -> 147 chunks)
    {
        dim3 grid(21, 16);
        gemm_mma<<<grid, 256, GEMM_SMEM>>>(
            (const char*)xtA, (const char*)xtB, Cbuf, nullptr, Ev, 0,
            (size_t)Ev * LDK2, (size_t)Ev * LDK2, (size_t)Ev * Ev,
            1 << 30, LDK2, 147, 1);
    }
    // pack C -> A layout (with mirror)
    {
        dim3 grid(1152, 16);
        pack_ct<<<grid, 256>>>(Cbuf, Cp);
    }
    // V2 = C @ [Wq|Wk]
    {
        dim3 grid(6 * 12, 16);
        gemm_mma<<<grid, 256, GEMM_SMEM>>>(
            (const char*)Cp, (const char*)wt1, V2, nullptr, 1536, 12,
            (size_t)Ev * LDK, 0, (size_t)Ev * 1536, 1 << 30, LDK, 36, 0);
    }
    // G + norms, softmax
    k_gram2<<<256, 256>>>(W_qkv, V2, gram, nrm);
    k_soft<<<256, 256>>>(gram, nrm, temp);

    // fold P_b^T
    {
        dim3 grid(6, 256);
        k_fold<<<grid, 256>>>(gram, W_proj, Pt2);
    }
    // W_b = Wv @ P_b
    {
        dim3 grid(36, 16);
        gemm_mma<<<grid, 256, GEMM_SMEM>>>(
            (const char*)wv2, (const char*)Pt2, Wb, nullptr, Ev, 6,
            0, (size_t)Ev * LDKU * 4, (size_t)Ev * Ev, 1 << 30, LDK, 36, 0);
    }
    // pack W_b^T (batched)
    {
        dim3 grid((Ev * 384) / 256, 16);
        pack_wt<<<grid, 256>>>(Wb, wbT, Ev, Ev,
                               (size_t)Ev * Ev, (size_t)Ev * LDKU);
    }
    // final: out_b = X_b @ W_b + b_proj
    {
        dim3 grid(25 * 6, 16);
        gemm_mma<<<grid, 256, GEMM_SMEM>>>(
            (const char*)x2, (const char*)wbT, outp, b_proj, Ev, 6,
            (size_t)Sv * LDK, (size_t)Ev * LDKU * 4, (size_t)Sv * Ev,
            Sv, LDK, 36, 0);
    }
}

// round 11
// speedup vs baseline: 3.4746x; 1.0831x over previous
#include <cuda_runtime.h>
#include <cuda_bf16.h>
#include <math.h>
#include <stdint.h>

// ---------------- problem constants ----------------
#define Bv 16
#define Sv 3136
#define Ev 768
#define Hv 16
#define Dv 48
#define NTOK (Bv * Sv)      // 50176
#define LDK 4608            // bytes per packed row, K=768 triplet (2304 bf16)
#define LDKU 1152           // u32 per packed row (K=768 triplet)
#define LDH 6272            // bytes per plain-bf16 row, K=3136
#define LDHU 1568           // u32 per plain row
#define NSTG 3
#define STG_BYTES 32768
#define GEMM_SMEM (NSTG * STG_BYTES)   // 98304

// ---------------- scratch (device globals) ----------------
__device__ uint32_t g_x2[(size_t)(NTOK + 128) * LDKU]; // packed x rows (A triplet)
__device__ uint32_t g_xtH[(size_t)Bv * Ev * LDHU];     // X^T hi, plain bf16
__device__ uint32_t g_xtL[(size_t)Bv * Ev * LDHU];     // X^T lo, plain bf16
__device__ float    g_R1[(size_t)Bv * Ev * Ev];        // H^T H (upper tiles)
__device__ float    g_R2[(size_t)Bv * Ev * Ev];        // H^T L (full)
__device__ uint32_t g_Cp[(size_t)Bv * Ev * LDKU];      // C packed (A triplet)
__device__ float    g_V2[(size_t)Bv * Ev * 1536];      // C @ [Wq|Wk]
__device__ uint32_t g_wt1[(size_t)1536 * LDKU];        // [Wq|Wk]^T packed (B)
__device__ uint32_t g_wv2[(size_t)Ev * LDKU];          // Wv rows packed (A)
__device__ float    g_gram[256 * 2304];                // 48x48 attn
__device__ uint32_t g_Pt2[(size_t)Bv * Ev * LDKU];     // P_b^T packed (B)
__device__ float    g_Wb[(size_t)Bv * Ev * Ev];        // W_b = Wv @ P_b
__device__ uint32_t g_wbT[(size_t)Bv * Ev * LDKU];     // W_b^T packed (B)

// ---------------- helpers ----------------
__device__ __forceinline__ uint32_t s2u(const void* p) {
    uint32_t a;
    asm("{ .reg .u64 t; cvta.to.shared.u64 t, %1; cvt.u32.u64 %0, t; }"
        : "=r"(a) : "l"(p));
    return a;
}
#define SWZ(o) ((o) ^ (((o) >> 3) & 0x70))

__device__ __forceinline__ void cpasync16(uint32_t s, const void* g) {
    asm volatile("cp.async.cg.shared.global [%0], [%1], 16;\n" :: "r"(s), "l"(g));
}
__device__ __forceinline__ void cp_commit() {
    asm volatile("cp.async.commit_group;\n");
}
template <int N> __device__ __forceinline__ void cp_wait() {
    asm volatile("cp.async.wait_group %0;\n" :: "n"(N));
}
__device__ __forceinline__ void ldm4(uint32_t& r0, uint32_t& r1, uint32_t& r2,
                                     uint32_t& r3, uint32_t a) {
    asm volatile("ldmatrix.sync.aligned.m8n8.x4.shared.b16 {%0,%1,%2,%3}, [%4];"
                 : "=r"(r0), "=r"(r1), "=r"(r2), "=r"(r3) : "r"(a));
}
__device__ __forceinline__ void mma16816(float* d, const uint32_t* a,
                                         const uint32_t* b) {
    asm volatile(
        "mma.sync.aligned.m16n8k16.row.col.f32.bf16.bf16.f32 "
        "{%0,%1,%2,%3}, {%4,%5,%6,%7}, {%8,%9}, {%0,%1,%2,%3};"
        : "+f"(d[0]), "+f"(d[1]), "+f"(d[2]), "+f"(d[3])
        : "r"(a[0]), "r"(a[1]), "r"(a[2]), "r"(a[3]), "r"(b[0]), "r"(b[1]));
}
__device__ __forceinline__ void split2(float x, uint32_t& h, uint32_t& l) {
    __nv_bfloat16 hb = __float2bfloat16(x);
    float rem = x - __bfloat162float(hb);
    __nv_bfloat16 lb = __float2bfloat16(rem);
    h = (uint32_t)__bfloat16_as_ushort(hb);
    l = (uint32_t)__bfloat16_as_ushort(lb);
}

// ---------------------------------------------------------------------------
// bf16 mma.sync GEMM (proven config): runtime K row bytes / chunk count,
// batching, M-row store guard, optional triangular 6x6 tile decode.
// ---------------------------------------------------------------------------
__global__ __launch_bounds__(256, 2) void gemm_mma(
    const char* __restrict__ A, const char* __restrict__ B,
    float* __restrict__ C, const float* __restrict__ bias, int N, int NT,
    size_t aStride, size_t bStride, size_t cStride, int Mrows,
    int kRowBytes, int nkch, int tri)
{
    extern __shared__ char sm[];
    const int tid  = threadIdx.x;
    const int wid  = tid >> 5, lane = tid & 31;
    const int wm   = wid & 3;
    const int wn   = wid >> 2;
    const int bat  = blockIdx.y;
    int bm, bn;
    if (tri) {
        int t = blockIdx.x, r = 0, rl = 6;
        while (t >= rl) { t -= rl; rl--; r++; }
        bm = r; bn = r + t;
    } else {
        bm = blockIdx.x / NT; bn = blockIdx.x % NT;
    }
    const uint32_t smb = s2u(sm);

    const char* Ab = A + (size_t)bat * aStride + (size_t)bm * 128 * kRowBytes;
    const char* Bb = B + (size_t)bat * bStride + (size_t)bn * 128 * kRowBytes;

    const int ldr = tid >> 1;
    const int ldc = (tid & 1) * 64;

    auto loadch = [&](int sp, int ck) {
        uint32_t sa = smb + sp * STG_BYTES;
        uint32_t sb = sa + 16384;
        const char* a0 = Ab + ck * 128;
        const char* b0 = Bb + ck * 128;
        #pragma unroll
        for (int i = 0; i < 4; i++) {
            int cb = ldc + i * 16;
            cpasync16(sa + SWZ(ldr * 128 + cb), a0 + (size_t)ldr * kRowBytes + cb);
            cpasync16(sb + SWZ(ldr * 128 + cb), b0 + (size_t)ldr * kRowBytes + cb);
        }
        cp_commit();
    };

    float acc[2][8][4];
    #pragma unroll
    for (int m = 0; m < 2; m++)
        #pragma unroll
        for (int n = 0; n < 8; n++)
            #pragma unroll
            for (int p = 0; p < 4; p++) acc[m][n][p] = 0.f;

    loadch(0, 0);
    loadch(1, 1);

    const int a_row = (lane & 7) + ((lane >> 3) & 1) * 8;
    const int a_cb  = (lane >> 4) * 16;
    const int b_row = (lane & 7) + (lane >> 4) * 8;
    const int b_cb  = ((lane >> 3) & 1) * 16;

    uint32_t af[2][2][4], bf[2][8][2];

    auto ldfrag = [&](uint32_t sa, uint32_t sb, int ks, int buf) {
        #pragma unroll
        for (int mb = 0; mb < 2; mb++) {
            int r = wm * 32 + mb * 16 + a_row;
            ldm4(af[buf][mb][0], af[buf][mb][1], af[buf][mb][2], af[buf][mb][3],
                 sa + SWZ(r * 128 + ks * 32 + a_cb));
        }
        #pragma unroll
        for (int nb2 = 0; nb2 < 4; nb2++) {
            int r = wn * 64 + nb2 * 16 + b_row;
            ldm4(bf[buf][2 * nb2][0], bf[buf][2 * nb2][1],
                 bf[buf][2 * nb2 + 1][0], bf[buf][2 * nb2 + 1][1],
                 sb + SWZ(r * 128 + ks * 32 + b_cb));
        }
    };

    for (int k = 0; k < nkch; k++) {
        cp_wait<1>();
        __syncthreads();

        int kp = k + 2;
        if (kp < nkch) loadch(kp % NSTG, kp);
        else cp_commit();

        uint32_t sa = smb + (k % NSTG) * STG_BYTES;
        uint32_t sb = sa + 16384;

        ldfrag(sa, sb, 0, 0);
        #pragma unroll
        for (int ks = 0; ks < 4; ks++) {
            int c = ks & 1;
            if (ks < 3) ldfrag(sa, sb, ks + 1, c ^ 1);
            #pragma unroll
            for (int mb = 0; mb < 2; mb++)
                #pragma unroll
                for (int nb = 0; nb < 8; nb++)
                    mma16816(acc[mb][nb], af[c][mb], bf[c][nb]);
        }
    }

    float* Cb = C + (size_t)bat * cStride
                + (size_t)(bm * 128 + wm * 32) * N + (size_t)bn * 128 + wn * 64;
    const int er = lane >> 2;
    const int ec = (lane & 3) * 2;
    const int rbase = bm * 128 + wm * 32;
    float bvs[8][2];
    #pragma unroll
    for (int nb = 0; nb < 8; nb++) {
        if (bias) {
            const float* bp = bias + (size_t)bn * 128 + wn * 64 + nb * 8 + ec;
            bvs[nb][0] = bp[0]; bvs[nb][1] = bp[1];
        } else { bvs[nb][0] = 0.f; bvs[nb][1] = 0.f; }
    }
    #pragma unroll
    for (int mb = 0; mb < 2; mb++) {
        int r0 = rbase + mb * 16 + er;
        bool w0 = r0 < Mrows, w1 = (r0 + 8) < Mrows;
        #pragma unroll
        for (int nb = 0; nb < 8; nb++) {
            int col = nb * 8 + ec;
            float2 v0 = {acc[mb][nb][0] + bvs[nb][0], acc[mb][nb][1] + bvs[nb][1]};
            float2 v1 = {acc[mb][nb][2] + bvs[nb][0], acc[mb][nb][3] + bvs[nb][1]};
            if (w0) *(float2*)(Cb + (size_t)(mb * 16 + er) * N + col) = v0;
            if (w1) *(float2*)(Cb + (size_t)(mb * 16 + er + 8) * N + col) = v1;
        }
    }
}

// ---------------------------------------------------------------------------
// Fused X packing: one pass produces x2 (row-major A-triplet), xtH, xtL
// (transposed plain-bf16 hi/lo). grid = (12 e-tiles, 49 s-tiles, 16 b).
// ---------------------------------------------------------------------------
__global__ __launch_bounds__(256) void pack_x(
    const float* __restrict__ x, uint32_t* __restrict__ x2,
    uint32_t* __restrict__ xtH, uint32_t* __restrict__ xtL)
{
    __shared__ float ts[64][65];
    const int e0 = blockIdx.x * 64, s0 = blockIdx.y * 64, b = blockIdx.z;
    const int tid = threadIdx.x;
    #pragma unroll
    for (int i = 0; i < 16; i++) {
        int idx = tid + i * 256;
        int sl = idx >> 6, el = idx & 63;
        ts[sl][el] = x[((size_t)b * Sv + s0 + sl) * Ev + e0 + el];
    }
    __syncthreads();
    // transposed hi/lo rows: item -> (el, s-pair)
    #pragma unroll
    for (int i = 0; i < 8; i++) {
        int item = tid + i * 256;
        int el = item >> 5, sp = item & 31;
        float v0 = ts[2 * sp][el], v1 = ts[2 * sp + 1][el];
        uint32_t h0, l0, h1, l1;
        split2(v0, h0, l0);
        split2(v1, h1, l1);
        size_t r = ((size_t)b * Ev + e0 + el) * LDHU + (s0 >> 1) + sp;
        xtH[r] = h0 | (h1 << 16);
        xtL[r] = l0 | (l1 << 16);
    }
    // row-major triplets: item -> (sl, e-pair)
    #pragma unroll
    for (int i = 0; i < 8; i++) {
        int item = tid + i * 256;
        int sl = item >> 5, pe = item & 31;
        float v0 = ts[sl][2 * pe], v1 = ts[sl][2 * pe + 1];
        uint32_t h0, l0, h1, l1;
        split2(v0, h0, l0);
        split2(v1, h1, l1);
        size_t o = ((size_t)b * Sv + s0 + sl) * LDKU + 3 * ((e0 >> 1) + pe);
        x2[o + 0] = h0 | (h0 << 16);
        x2[o + 1] = l0 | (h1 << 16);
        x2[o + 2] = h1 | (l1 << 16);
    }
}

// transpose-pack of W columns -> B-layout triplet rows (batched)
__global__ void pack_wt(const float* __restrict__ W, uint32_t* __restrict__ out,
                        int ncols, int stride, size_t wStride, size_t oStride)
{
    int t = blockIdx.x * 256 + threadIdx.x;
    if (t >= ncols * 384) return;
    const float* Wb = W + (size_t)blockIdx.y * wStride;
    uint32_t* ob = out + (size_t)blockIdx.y * oStride;
    int n = t / 384, kp = t % 384;
    float x0 = Wb[(size_t)(2 * kp) * stride + n];
    float x1 = Wb[(size_t)(2 * kp + 1) * stride + n];
    uint32_t h0, l0, h1, l1;
    split2(x0, h0, l0);
    split2(x1, h1, l1);
    uint32_t* o = ob + (size_t)n * LDKU + 3 * kp;
    o[0] = h0 | (l0 << 16);
    o[1] = h0 | (h1 << 16);
    o[2] = l1 | (h1 << 16);
}

// pack Wv rows (A triplet): Wv = W_qkv[:, 1536:2304]
__global__ void pack_wv(const float* __restrict__ Wqkv, uint32_t* __restrict__ out)
{
    int t = blockIdx.x * 256 + threadIdx.x;
    if (t >= Ev * 384) return;
    int e = t / 384, c = t % 384;
    float x0 = Wqkv[(size_t)e * 2304 + 1536 + 2 * c];
    float x1 = Wqkv[(size_t)e * 2304 + 1536 + 2 * c + 1];
    uint32_t h0, l0, h1, l1;
    split2(x0, h0, l0);
    split2(x1, h1, l1);
    uint32_t* o = out + (size_t)e * LDKU + 3 * c;
    o[0] = h0 | (h0 << 16);
    o[1] = l0 | (h1 << 16);
    o[2] = h1 | (l1 << 16);
}

// Assemble C = R1(upper,mirrored) + R2 + R2^T and pack as A-triplet rows.
__global__ void pack_ct(const float* __restrict__ R1, const float* __restrict__ R2,
                        uint32_t* __restrict__ out)
{
    int t = blockIdx.x * 256 + threadIdx.x;   // < 768*384
    const float* R1b = R1 + (size_t)blockIdx.y * Ev * Ev;
    const float* R2b = R2 + (size_t)blockIdx.y * Ev * Ev;
    uint32_t* ob = out + (size_t)blockIdx.y * Ev * LDKU;
    int e1 = t / 384, p = t % 384;
    int t1 = e1 >> 7;
    float v[2];
    #pragma unroll
    for (int q = 0; q < 2; q++) {
        int e2 = 2 * p + q;
        float r1 = (t1 <= (e2 >> 7)) ? R1b[(size_t)e1 * Ev + e2]
                                     : R1b[(size_t)e2 * Ev + e1];
        v[q] = r1 + R2b[(size_t)e1 * Ev + e2] + R2b[(size_t)e2 * Ev + e1];
    }
    uint32_t h0, l0, h1, l1;
    split2(v[0], h0, l0);
    split2(v[1], h1, l1);
    uint32_t* o = ob + (size_t)e1 * LDKU + 3 * p;
    o[0] = h0 | (h0 << 16);
    o[1] = l0 | (h1 << 16);
    o[2] = h1 | (l1 << 16);
}

// ---------------------------------------------------------------------------
// Fused G + norms + softmax. One block per (b,h).
// G_bh = Wq_h^T U ; nq2 = col-dots Wq.Tq ; nk2 = col-dots Wk.U
// where [Tq|U] = V2 = C @ [Wq|Wk]. Softmax in-place, writes attn to gram.
// ---------------------------------------------------------------------------
#define CH2 48
__global__ __launch_bounds__(256) void k_gs(
    const float* __restrict__ Wqkv, const float* __restrict__ V2,
    const float* __restrict__ temp, float* __restrict__ gram)
{
    __shared__ float Wqs[Dv][CH2 + 1];
    __shared__ float Wks[Dv][CH2 + 1];
    __shared__ float Tqs[Dv][CH2 + 1];
    __shared__ float Us[Dv][CH2 + 1];
    __shared__ float nr[96];
    float (*Gs)[CH2 + 1] = Wqs;   // reuse after accumulation
    const int bh = blockIdx.x;
    const int b = bh >> 4, h = bh & 15;
    const int tid = threadIdx.x;
    const int tx = tid & 15, ty = tid >> 4;

    float acc[3][3];
    #pragma unroll
    for (int r = 0; r < 3; r++)
        #pragma unroll
        for (int c = 0; c < 3; c++) acc[r][c] = 0.f;
    float na = 0.f;

    for (int e0 = 0; e0 < Ev; e0 += CH2) {
        for (int idx = tid; idx < Dv * CH2; idx += 256) {
            int i = idx % Dv, el = idx / Dv;
            int e = e0 + el;
            const float* wrow = Wqkv + (size_t)e * 2304 + h * Dv;
            const float* vrow = V2 + ((size_t)b * Ev + e) * 1536 + h * Dv;
            Wqs[i][el] = wrow[i];
            Wks[i][el] = wrow[768 + i];
            Tqs[i][el] = vrow[i];
            Us[i][el]  = vrow[768 + i];
        }
        __syncthreads();
        #pragma unroll 4
        for (int el = 0; el < CH2; el++) {
            float qv[3], uv[3];
            #pragma unroll
            for (int r = 0; r < 3; r++) qv[r] = Wqs[3 * ty + r][el];
            #pragma unroll
            for (int c = 0; c < 3; c++) uv[c] = Us[3 * tx + c][el];
            #pragma unroll
            for (int r = 0; r < 3; r++)
                #pragma unroll
                for (int c = 0; c < 3; c++)
                    acc[r][c] = fmaf(qv[r], uv[c], acc[r][c]);
        }
        if (tid < 2 * Dv) {
            float a = 0.f;
            if (tid < Dv) {
                #pragma unroll 8
                for (int el = 0; el < CH2; el++)
                    a = fmaf(Wqs[tid][el], Tqs[tid][el], a);
            } else {
                int j = tid - Dv;
                #pragma unroll 8
                for (int el = 0; el < CH2; el++)
                    a = fmaf(Wks[j][el], Us[j][el], a);
            }
            na += a;
        }
        __syncthreads();
    }
    // stash G and norms in smem
    #pragma unroll
    for (int r = 0; r < 3; r++)
        #pragma unroll
        for (int c = 0; c < 3; c++)
            Gs[3 * ty + r][3 * tx + c] = acc[r][c];
    if (tid < 96) nr[tid] = fmaxf(sqrtf(na), 1e-12f);
    __syncthreads();

    // softmax
    const float T = temp[h];
    const int warp = tid >> 5, lane = tid & 31;
    for (int i = warp; i < Dv; i += 8) {
        float inq = T / nr[i];
        int j0 = lane, j1 = lane + 32;
        float v0 = Gs[i][j0] * inq / nr[Dv + j0];
        float v1 = (j1 < Dv) ? Gs[i][j1] * inq / nr[Dv + j1] : -INFINITY;
        float m = fmaxf(v0, v1);
        #pragma unroll
        for (int o = 16; o; o >>= 1) m = fmaxf(m, __shfl_xor_sync(~0u, m, o));
        float e0 = expf(v0 - m);
        float e1 = (j1 < Dv) ? expf(v1 - m) : 0.f;
        float ss = e0 + e1;
        #pragma unroll
        for (int o = 16; o; o >>= 1) ss += __shfl_xor_sync(~0u, ss, o);
        float inv = 1.f / ss;
        gram[(size_t)bh * 2304 + i * Dv + j0] = e0 * inv;
        if (j1 < Dv) gram[(size_t)bh * 2304 + i * Dv + j1] = e1 * inv;
    }
}

// Fold: P_b^T[n,(h,j)] = sum_i attn_bh[i,j] * W_proj[(h,i), n] (packed B)
__global__ __launch_bounds__(256) void k_fold(
    const float* __restrict__ attn, const float* __restrict__ Wp,
    uint32_t* __restrict__ Pt2)
{
    __shared__ float As[Dv][Dv + 1];
    __shared__ float Ws[Dv][128];
    const int nb = blockIdx.x;
    const int bh = blockIdx.y;
    const int b = bh >> 4, h = bh & 15;
    const int tid = threadIdx.x;
    const int tx = tid & 127;
    const int tz = tid >> 7;

    for (int idx = tid; idx < Dv * Dv; idx += 256)
        As[idx / Dv][idx % Dv] = attn[(size_t)bh * 2304 + idx];
    for (int idx = tid; idx < Dv * 128; idx += 256) {
        int i = idx >> 7, c = idx & 127;
        Ws[i][c] = Wp[(size_t)(h * Dv + i) * Ev + nb * 128 + c];
    }
    __syncthreads();

    float acc[24];
    #pragma unroll
    for (int j = 0; j < 24; j++) acc[j] = 0.f;
    #pragma unroll 4
    for (int i = 0; i < Dv; i++) {
        float a = Ws[i][tx];
        #pragma unroll
        for (int j = 0; j < 24; j++)
            acc[j] = fmaf(As[i][tz * 24 + j], a, acc[j]);
    }

    int n = nb * 128 + tx;
    uint32_t* ob = Pt2 + (size_t)b * Ev * LDKU + (size_t)n * LDKU;
    #pragma unroll
    for (int t = 0; t < 12; t++) {
        uint32_t h0, l0, h1, l1;
        split2(acc[2 * t], h0, l0);
        split2(acc[2 * t + 1], h1, l1);
        uint32_t* o = ob + 3 * (h * 24 + tz * 12 + t);
        o[0] = h0 | (l0 << 16);
        o[1] = h0 | (h1 << 16);
        o[2] = l1 | (h1 << 16);
    }
}

// ---------------------------------------------------------------------------
// Launch
// ---------------------------------------------------------------------------
extern "C" void kernel_launch(void* const* d_in, const int* in_sizes, int n_in,
                              void* d_out, int out_size)
{
    const float* x      = (const float*)d_in[0];
    const float* W_qkv  = (const float*)d_in[1];
    const float* W_proj = (const float*)d_in[2];
    const float* b_proj = (const float*)d_in[3];
    const float* temp   = (const float*)d_in[4];
    float* outp = (float*)d_out;

    uint32_t *x2, *xtH, *xtL, *Cp, *wt1, *wv2, *Pt2, *wbT;
    float *R1, *R2, *V2, *gram, *Wb;
    cudaGetSymbolAddress((void**)&x2, g_x2);
    cudaGetSymbolAddress((void**)&xtH, g_xtH);
    cudaGetSymbolAddress((void**)&xtL, g_xtL);
    cudaGetSymbolAddress((void**)&Cp, g_Cp);
    cudaGetSymbolAddress((void**)&wt1, g_wt1);
    cudaGetSymbolAddress((void**)&wv2, g_wv2);
    cudaGetSymbolAddress((void**)&Pt2, g_Pt2);
    cudaGetSymbolAddress((void**)&wbT, g_wbT);
    cudaGetSymbolAddress((void**)&R1, g_R1);
    cudaGetSymbolAddress((void**)&R2, g_R2);
    cudaGetSymbolAddress((void**)&V2, g_V2);
    cudaGetSymbolAddress((void**)&gram, g_gram);
    cudaGetSymbolAddress((void**)&Wb, g_Wb);

    cudaFuncSetAttribute(gemm_mma, cudaFuncAttributeMaxDynamicSharedMemorySize,
                         GEMM_SMEM);

    // fused X packing + weight packing
    {
        dim3 grid(12, 49, 16);
        pack_x<<<grid, 256>>>(x, x2, xtH, xtL);
    }
    pack_wt<<<(1536 * 384) / 256, 256>>>(W_qkv, wt1, 1536, 2304, 0, 0);
    pack_wv<<<(Ev * 384) / 256, 256>>>(W_qkv, wv2);

    // R1 = H^T H (upper tiles), R2 = H^T L (full). Plain bf16, K=3136.
    {
        dim3 grid(21, 16);
        gemm_mma<<<grid, 256, GEMM_SMEM>>>(
            (const char*)xtH, (const char*)xtH, R1, nullptr, Ev, 0,
            (size_t)Ev * LDH, (size_t)Ev * LDH, (size_t)Ev * Ev,
            1 << 30, LDH, 49, 1);
    }
    {
        dim3 grid(36, 16);
        gemm_mma<<<grid, 256, GEMM_SMEM>>>(
            (const char*)xtH, (const char*)xtL, R2, nullptr, Ev, 6,
            (size_t)Ev * LDH, (size_t)Ev * LDH, (size_t)Ev * Ev,
            1 << 30, LDH, 49, 0);
    }
    // C = R1 + R2 + R2^T, packed A-triplet
    {
        dim3 grid(1152, 16);
        pack_ct<<<grid, 256>>>(R1, R2, Cp);
    }
    // V2 = C @ [Wq|Wk]
    {
        dim3 grid(6 * 12, 16);
        gemm_mma<<<grid, 256, GEMM_SMEM>>>(
            (const char*)Cp, (const char*)wt1, V2, nullptr, 1536, 12,
            (size_t)Ev * LDK, 0, (size_t)Ev * 1536, 1 << 30, LDK, 36, 0);
    }
    // G + norms + softmax (fused)
    k_gs<<<256, 256>>>(W_qkv, V2, temp, gram);

    // fold P_b^T
    {
        dim3 grid(6, 256);
        k_fold<<<grid, 256>>>(gram, W_proj, Pt2);
    }
    // W_b = Wv @ P_b
    {
        dim3 grid(36, 16);
        gemm_mma<<<grid, 256, GEMM_SMEM>>>(
            (const char*)wv2, (const char*)Pt2, Wb, nullptr, Ev, 6,
            0, (size_t)Ev * LDKU * 4, (size_t)Ev * Ev, 1 << 30, LDK, 36, 0);
    }
    // pack W_b^T (batched)
    {
        dim3 grid((Ev * 384) / 256, 16);
        pack_wt<<<grid, 256>>>(Wb, wbT, Ev, Ev,
                               (size_t)Ev * Ev, (size_t)Ev * LDKU);
    }
    // final: out_b = X_b @ W_b + b_proj
    {
        dim3 grid(25 * 6, 16);
        gemm_mma<<<grid, 256, GEMM_SMEM>>>(
            (const char*)x2, (const char*)wbT, outp, b_proj, Ev, 6,
            (size_t)Sv * LDK, (size_t)Ev * LDKU * 4, (size_t)Sv * Ev,
            Sv, LDK, 36, 0);
    }
}

// round 12
// speedup vs baseline: 3.5432x; 1.0197x over previous
#include <cuda_runtime.h>
#include <cuda_bf16.h>
#include <math.h>
#include <stdint.h>

// ---------------- problem constants ----------------
#define Bv 16
#define Sv 3136
#define Ev 768
#define Hv 16
#define Dv 48
#define NTOK (Bv * Sv)      // 50176
#define LDK 4608            // bytes per packed row, K=768 triplet (2304 bf16)
#define LDKU 1152           // u32 per packed row (K=768 triplet)
#define LDH 6272            // bytes per plain-bf16 row, K=3136
#define LDHU 1568           // u32 per plain row
#define NSTG 3
#define STG_BYTES 32768
#define GEMM_SMEM (NSTG * STG_BYTES)   // 98304

// ---------------- scratch (device globals) ----------------
__device__ uint32_t g_x2[(size_t)(NTOK + 128) * LDKU]; // packed x rows (A triplet)
__device__ uint32_t g_xtH[(size_t)Bv * Ev * LDHU];     // X^T hi, plain bf16
__device__ uint32_t g_xtL[(size_t)Bv * Ev * LDHU];     // X^T lo, plain bf16
__device__ float    g_R1[(size_t)Bv * Ev * Ev];        // H^T H (upper tiles)
__device__ float    g_R2[(size_t)Bv * Ev * Ev];        // H^T L (full)
__device__ uint32_t g_Cp[(size_t)Bv * Ev * LDKU];      // C packed (A triplet)
__device__ float    g_V2[(size_t)Bv * Ev * 1536];      // C @ [Wq|Wk]
__device__ uint32_t g_wt1[(size_t)1536 * LDKU];        // [Wq|Wk]^T packed (B)
__device__ uint32_t g_wv2[(size_t)Ev * LDKU];          // Wv rows packed (B layout)
__device__ float    g_gram[256 * 2304];                // 48x48 attn
__device__ uint32_t g_Pt2[(size_t)Bv * Ev * LDKU];     // P_b^T packed (A layout)
__device__ uint32_t g_wbT[(size_t)Bv * Ev * LDKU];     // W_b^T packed (B layout)

// ---------------- helpers ----------------
__device__ __forceinline__ uint32_t s2u(const void* p) {
    uint32_t a;
    asm("{ .reg .u64 t; cvta.to.shared.u64 t, %1; cvt.u32.u64 %0, t; }"
        : "=r"(a) : "l"(p));
    return a;
}
#define SWZ(o) ((o) ^ (((o) >> 3) & 0x70))

__device__ __forceinline__ void cpasync16(uint32_t s, const void* g) {
    asm volatile("cp.async.cg.shared.global [%0], [%1], 16;\n" :: "r"(s), "l"(g));
}
__device__ __forceinline__ void cp_commit() {
    asm volatile("cp.async.commit_group;\n");
}
template <int N> __device__ __forceinline__ void cp_wait() {
    asm volatile("cp.async.wait_group %0;\n" :: "n"(N));
}
__device__ __forceinline__ void ldm4(uint32_t& r0, uint32_t& r1, uint32_t& r2,
                                     uint32_t& r3, uint32_t a) {
    asm volatile("ldmatrix.sync.aligned.m8n8.x4.shared.b16 {%0,%1,%2,%3}, [%4];"
                 : "=r"(r0), "=r"(r1), "=r"(r2), "=r"(r3) : "r"(a));
}
__device__ __forceinline__ void mma16816(float* d, const uint32_t* a,
                                         const uint32_t* b) {
    asm volatile(
        "mma.sync.aligned.m16n8k16.row.col.f32.bf16.bf16.f32 "
        "{%0,%1,%2,%3}, {%4,%5,%6,%7}, {%8,%9}, {%0,%1,%2,%3};"
        : "+f"(d[0]), "+f"(d[1]), "+f"(d[2]), "+f"(d[3])
        : "r"(a[0]), "r"(a[1]), "r"(a[2]), "r"(a[3]), "r"(b[0]), "r"(b[1]));
}
__device__ __forceinline__ void split2(float x, uint32_t& h, uint32_t& l) {
    __nv_bfloat16 hb = __float2bfloat16(x);
    float rem = x - __bfloat162float(hb);
    __nv_bfloat16 lb = __float2bfloat16(rem);
    h = (uint32_t)__bfloat16_as_ushort(hb);
    l = (uint32_t)__bfloat16_as_ushort(lb);
}

// ---------------------------------------------------------------------------
// bf16 mma.sync GEMM (proven config). Extensions:
//  tri>0 : merged launch — blockIdx.x < tri does triangular tiles on (A,B)->C,
//          blockIdx.x >= tri does rectangular tiles on (A,Balt)->Calt (NT=6).
//  packC : epilogue writes B-layout bf16 triplets into (uint32_t*)C
//          (row stride LDKU u32; cStride counted in u32 elements).
// ---------------------------------------------------------------------------
__global__ __launch_bounds__(256, 2) void gemm_mma(
    const char* __restrict__ A, const char* __restrict__ B,
    float* __restrict__ C, const float* __restrict__ bias, int N, int NT,
    size_t aStride, size_t bStride, size_t cStride, int Mrows,
    int kRowBytes, int nkch, int tri,
    const char* __restrict__ Balt, float* __restrict__ Calt, int packC)
{
    extern __shared__ char sm[];
    const int tid  = threadIdx.x;
    const int wid  = tid >> 5, lane = tid & 31;
    const int wm   = wid & 3;
    const int wn   = wid >> 2;
    const int bat  = blockIdx.y;
    int bm, bn;
    const char* Bsel = B;
    float* Csel = C;
    if (tri > 0) {
        if ((int)blockIdx.x < tri) {
            int t = blockIdx.x, r = 0, rl = 6;
            while (t >= rl) { t -= rl; rl--; r++; }
            bm = r; bn = r + t;
        } else {
            int t = blockIdx.x - tri;
            bm = t / 6; bn = t % 6;
            Bsel = Balt; Csel = Calt;
        }
    } else {
        bm = blockIdx.x / NT; bn = blockIdx.x % NT;
    }
    const uint32_t smb = s2u(sm);

    const char* Ab = A + (size_t)bat * aStride + (size_t)bm * 128 * kRowBytes;
    const char* Bb = Bsel + (size_t)bat * bStride + (size_t)bn * 128 * kRowBytes;

    const int ldr = tid >> 1;
    const int ldc = (tid & 1) * 64;

    auto loadch = [&](int sp, int ck) {
        uint32_t sa = smb + sp * STG_BYTES;
        uint32_t sb = sa + 16384;
        const char* a0 = Ab + ck * 128;
        const char* b0 = Bb + ck * 128;
        #pragma unroll
        for (int i = 0; i < 4; i++) {
            int cb = ldc + i * 16;
            cpasync16(sa + SWZ(ldr * 128 + cb), a0 + (size_t)ldr * kRowBytes + cb);
            cpasync16(sb + SWZ(ldr * 128 + cb), b0 + (size_t)ldr * kRowBytes + cb);
        }
        cp_commit();
    };

    float acc[2][8][4];
    #pragma unroll
    for (int m = 0; m < 2; m++)
        #pragma unroll
        for (int n = 0; n < 8; n++)
            #pragma unroll
            for (int p = 0; p < 4; p++) acc[m][n][p] = 0.f;

    loadch(0, 0);
    loadch(1, 1);

    const int a_row = (lane & 7) + ((lane >> 3) & 1) * 8;
    const int a_cb  = (lane >> 4) * 16;
    const int b_row = (lane & 7) + (lane >> 4) * 8;
    const int b_cb  = ((lane >> 3) & 1) * 16;

    uint32_t af[2][2][4], bf[2][8][2];

    auto ldfrag = [&](uint32_t sa, uint32_t sb, int ks, int buf) {
        #pragma unroll
        for (int mb = 0; mb < 2; mb++) {
            int r = wm * 32 + mb * 16 + a_row;
            ldm4(af[buf][mb][0], af[buf][mb][1], af[buf][mb][2], af[buf][mb][3],
                 sa + SWZ(r * 128 + ks * 32 + a_cb));
        }
        #pragma unroll
        for (int nb2 = 0; nb2 < 4; nb2++) {
            int r = wn * 64 + nb2 * 16 + b_row;
            ldm4(bf[buf][2 * nb2][0], bf[buf][2 * nb2][1],
                 bf[buf][2 * nb2 + 1][0], bf[buf][2 * nb2 + 1][1],
                 sb + SWZ(r * 128 + ks * 32 + b_cb));
        }
    };

    for (int k = 0; k < nkch; k++) {
        cp_wait<1>();
        __syncthreads();

        int kp = k + 2;
        if (kp < nkch) loadch(kp % NSTG, kp);
        else cp_commit();

        uint32_t sa = smb + (k % NSTG) * STG_BYTES;
        uint32_t sb = sa + 16384;

        ldfrag(sa, sb, 0, 0);
        #pragma unroll
        for (int ks = 0; ks < 4; ks++) {
            int c = ks & 1;
            if (ks < 3) ldfrag(sa, sb, ks + 1, c ^ 1);
            #pragma unroll
            for (int mb = 0; mb < 2; mb++)
                #pragma unroll
                for (int nb = 0; nb < 8; nb++)
                    mma16816(acc[mb][nb], af[c][mb], bf[c][nb]);
        }
    }

    const int er = lane >> 2;
    const int ec = (lane & 3) * 2;
    const int rbase = bm * 128 + wm * 32;

    if (packC) {
        // write B-layout bf16 triplets: row = output row, pair = col/2
        uint32_t* Cpk = (uint32_t*)Csel + (size_t)bat * cStride;
        #pragma unroll
        for (int mb = 0; mb < 2; mb++) {
            int r0 = rbase + mb * 16 + er;
            #pragma unroll
            for (int nb = 0; nb < 8; nb++) {
                int col = bn * 128 + wn * 64 + nb * 8 + ec;   // even
                uint32_t h0, l0, h1, l1;
                split2(acc[mb][nb][0], h0, l0);
                split2(acc[mb][nb][1], h1, l1);
                uint32_t* o = Cpk + (size_t)r0 * LDKU + 3 * (col >> 1);
                o[0] = h0 | (l0 << 16);
                o[1] = h0 | (h1 << 16);
                o[2] = l1 | (h1 << 16);
                split2(acc[mb][nb][2], h0, l0);
                split2(acc[mb][nb][3], h1, l1);
                uint32_t* o2 = Cpk + (size_t)(r0 + 8) * LDKU + 3 * (col >> 1);
                o2[0] = h0 | (l0 << 16);
                o2[1] = h0 | (h1 << 16);
                o2[2] = l1 | (h1 << 16);
            }
        }
        return;
    }

    float* Cb = Csel + (size_t)bat * cStride
                + (size_t)rbase * N + (size_t)bn * 128 + wn * 64;
    float bvs[8][2];
    #pragma unroll
    for (int nb = 0; nb < 8; nb++) {
        if (bias) {
            const float* bp = bias + (size_t)bn * 128 + wn * 64 + nb * 8 + ec;
            bvs[nb][0] = bp[0]; bvs[nb][1] = bp[1];
        } else { bvs[nb][0] = 0.f; bvs[nb][1] = 0.f; }
    }
    #pragma unroll
    for (int mb = 0; mb < 2; mb++) {
        int r0 = rbase + mb * 16 + er;
        bool w0 = r0 < Mrows, w1 = (r0 + 8) < Mrows;
        #pragma unroll
        for (int nb = 0; nb < 8; nb++) {
            int col = nb * 8 + ec;
            float2 v0 = {acc[mb][nb][0] + bvs[nb][0], acc[mb][nb][1] + bvs[nb][1]};
            float2 v1 = {acc[mb][nb][2] + bvs[nb][0], acc[mb][nb][3] + bvs[nb][1]};
            if (w0) *(float2*)(Cb + (size_t)(mb * 16 + er) * N + col) = v0;
            if (w1) *(float2*)(Cb + (size_t)(mb * 16 + er + 8) * N + col) = v1;
        }
    }
}

// ---------------------------------------------------------------------------
// Fused X packing: x2 (row-major A-triplet), xtH, xtL (transposed hi/lo).
// grid = (12 e-tiles, 49 s-tiles, 16 b).
// ---------------------------------------------------------------------------
__global__ __launch_bounds__(256) void pack_x(
    const float* __restrict__ x, uint32_t* __restrict__ x2,
    uint32_t* __restrict__ xtH, uint32_t* __restrict__ xtL)
{
    __shared__ float ts[64][65];
    const int e0 = blockIdx.x * 64, s0 = blockIdx.y * 64, b = blockIdx.z;
    const int tid = threadIdx.x;
    #pragma unroll
    for (int i = 0; i < 16; i++) {
        int idx = tid + i * 256;
        int sl = idx >> 6, el = idx & 63;
        ts[sl][el] = x[((size_t)b * Sv + s0 + sl) * Ev + e0 + el];
    }
    __syncthreads();
    #pragma unroll
    for (int i = 0; i < 8; i++) {
        int item = tid + i * 256;
        int el = item >> 5, sp = item & 31;
        float v0 = ts[2 * sp][el], v1 = ts[2 * sp + 1][el];
        uint32_t h0, l0, h1, l1;
        split2(v0, h0, l0);
        split2(v1, h1, l1);
        size_t r = ((size_t)b * Ev + e0 + el) * LDHU + (s0 >> 1) + sp;
        xtH[r] = h0 | (h1 << 16);
        xtL[r] = l0 | (l1 << 16);
    }
    #pragma unroll
    for (int i = 0; i < 8; i++) {
        int item = tid + i * 256;
        int sl = item >> 5, pe = item & 31;
        float v0 = ts[sl][2 * pe], v1 = ts[sl][2 * pe + 1];
        uint32_t h0, l0, h1, l1;
        split2(v0, h0, l0);
        split2(v1, h1, l1);
        size_t o = ((size_t)b * Sv + s0 + sl) * LDKU + 3 * ((e0 >> 1) + pe);
        x2[o + 0] = h0 | (h0 << 16);
        x2[o + 1] = l0 | (h1 << 16);
        x2[o + 2] = h1 | (l1 << 16);
    }
}

// transpose-pack of W columns -> B-layout triplet rows
__global__ void pack_wt(const float* __restrict__ W, uint32_t* __restrict__ out,
                        int ncols, int stride)
{
    int t = blockIdx.x * 256 + threadIdx.x;
    if (t >= ncols * 384) return;
    int n = t / 384, kp = t % 384;
    float x0 = W[(size_t)(2 * kp) * stride + n];
    float x1 = W[(size_t)(2 * kp + 1) * stride + n];
    uint32_t h0, l0, h1, l1;
    split2(x0, h0, l0);
    split2(x1, h1, l1);
    uint32_t* o = out + (size_t)n * LDKU + 3 * kp;
    o[0] = h0 | (l0 << 16);
    o[1] = h0 | (h1 << 16);
    o[2] = l1 | (h1 << 16);
}

// pack Wv rows in B layout: Wv = W_qkv[:, 1536:2304]
__global__ void pack_wv(const float* __restrict__ Wqkv, uint32_t* __restrict__ out)
{
    int t = blockIdx.x * 256 + threadIdx.x;
    if (t >= Ev * 384) return;
    int e = t / 384, c = t % 384;
    float x0 = Wqkv[(size_t)e * 2304 + 1536 + 2 * c];
    float x1 = Wqkv[(size_t)e * 2304 + 1536 + 2 * c + 1];
    uint32_t h0, l0, h1, l1;
    split2(x0, h0, l0);
    split2(x1, h1, l1);
    uint32_t* o = out + (size_t)e * LDKU + 3 * c;
    o[0] = h0 | (l0 << 16);
    o[1] = h0 | (h1 << 16);
    o[2] = l1 | (h1 << 16);
}

// Assemble C = R1(upper,mirrored) + R2 + R2^T and pack as A-triplet rows.
__global__ void pack_ct(const float* __restrict__ R1, const float* __restrict__ R2,
                        uint32_t* __restrict__ out)
{
    int t = blockIdx.x * 256 + threadIdx.x;   // < 768*384
    const float* R1b = R1 + (size_t)blockIdx.y * Ev * Ev;
    const float* R2b = R2 + (size_t)blockIdx.y * Ev * Ev;
    uint32_t* ob = out + (size_t)blockIdx.y * Ev * LDKU;
    int e1 = t / 384, p = t % 384;
    int t1 = e1 >> 7;
    float v[2];
    #pragma unroll
    for (int q = 0; q < 2; q++) {
        int e2 = 2 * p + q;
        float r1 = (t1 <= (e2 >> 7)) ? R1b[(size_t)e1 * Ev + e2]
                                     : R1b[(size_t)e2 * Ev + e1];
        v[q] = r1 + R2b[(size_t)e1 * Ev + e2] + R2b[(size_t)e2 * Ev + e1];
    }
    uint32_t h0, l0, h1, l1;
    split2(v[0], h0, l0);
    split2(v[1], h1, l1);
    uint32_t* o = ob + (size_t)e1 * LDKU + 3 * p;
    o[0] = h0 | (h0 << 16);
    o[1] = l0 | (h1 << 16);
    o[2] = h1 | (l1 << 16);
}

// ---------------------------------------------------------------------------
// Fused G + norms + softmax. One block per (b,h).
// ---------------------------------------------------------------------------
#define CH2 48
__global__ __launch_bounds__(256) void k_gs(
    const float* __restrict__ Wqkv, const float* __restrict__ V2,
    const float* __restrict__ temp, float* __restrict__ gram)
{
    __shared__ float Wqs[Dv][CH2 + 1];
    __shared__ float Wks[Dv][CH2 + 1];
    __shared__ float Tqs[Dv][CH2 + 1];
    __shared__ float Us[Dv][CH2 + 1];
    __shared__ float nr[96];
    float (*Gs)[CH2 + 1] = Wqs;
    const int bh = blockIdx.x;
    const int b = bh >> 4, h = bh & 15;
    const int tid = threadIdx.x;
    const int tx = tid & 15, ty = tid >> 4;

    float acc[3][3];
    #pragma unroll
    for (int r = 0; r < 3; r++)
        #pragma unroll
        for (int c = 0; c < 3; c++) acc[r][c] = 0.f;
    float na = 0.f;

    for (int e0 = 0; e0 < Ev; e0 += CH2) {
        for (int idx = tid; idx < Dv * CH2; idx += 256) {
            int i = idx % Dv, el = idx / Dv;
            int e = e0 + el;
            const float* wrow = Wqkv + (size_t)e * 2304 + h * Dv;
            const float* vrow = V2 + ((size_t)b * Ev + e) * 1536 + h * Dv;
            Wqs[i][el] = wrow[i];
            Wks[i][el] = wrow[768 + i];
            Tqs[i][el] = vrow[i];
            Us[i][el]  = vrow[768 + i];
        }
        __syncthreads();
        #pragma unroll 4
        for (int el = 0; el < CH2; el++) {
            float qv[3], uv[3];
            #pragma unroll
            for (int r = 0; r < 3; r++) qv[r] = Wqs[3 * ty + r][el];
            #pragma unroll
            for (int c = 0; c < 3; c++) uv[c] = Us[3 * tx + c][el];
            #pragma unroll
            for (int r = 0; r < 3; r++)
                #pragma unroll
                for (int c = 0; c < 3; c++)
                    acc[r][c] = fmaf(qv[r], uv[c], acc[r][c]);
        }
        if (tid < 2 * Dv) {
            float a = 0.f;
            if (tid < Dv) {
                #pragma unroll 8
                for (int el = 0; el < CH2; el++)
                    a = fmaf(Wqs[tid][el], Tqs[tid][el], a);
            } else {
                int j = tid - Dv;
                #pragma unroll 8
                for (int el = 0; el < CH2; el++)
                    a = fmaf(Wks[j][el], Us[j][el], a);
            }
            na += a;
        }
        __syncthreads();
    }
    #pragma unroll
    for (int r = 0; r < 3; r++)
        #pragma unroll
        for (int c = 0; c < 3; c++)
            Gs[3 * ty + r][3 * tx + c] = acc[r][c];
    if (tid < 96) nr[tid] = fmaxf(sqrtf(na), 1e-12f);
    __syncthreads();

    const float T = temp[h];
    const int warp = tid >> 5, lane = tid & 31;
    for (int i = warp; i < Dv; i += 8) {
        float inq = T / nr[i];
        int j0 = lane, j1 = lane + 32;
        float v0 = Gs[i][j0] * inq / nr[Dv + j0];
        float v1 = (j1 < Dv) ? Gs[i][j1] * inq / nr[Dv + j1] : -INFINITY;
        float m = fmaxf(v0, v1);
        #pragma unroll
        for (int o = 16; o; o >>= 1) m = fmaxf(m, __shfl_xor_sync(~0u, m, o));
        float e0 = expf(v0 - m);
        float e1 = (j1 < Dv) ? expf(v1 - m) : 0.f;
        float ss = e0 + e1;
        #pragma unroll
        for (int o = 16; o; o >>= 1) ss += __shfl_xor_sync(~0u, ss, o);
        float inv = 1.f / ss;
        gram[(size_t)bh * 2304 + i * Dv + j0] = e0 * inv;
        if (j1 < Dv) gram[(size_t)bh * 2304 + i * Dv + j1] = e1 * inv;
    }
}

// Fold: P_b^T[n,(h,j)] = sum_i attn_bh[i,j] * W_proj[(h,i), n], A-layout packed.
__global__ __launch_bounds__(256) void k_fold(
    const float* __restrict__ attn, const float* __restrict__ Wp,
    uint32_t* __restrict__ Pt2)
{
    __shared__ float As[Dv][Dv + 1];
    __shared__ float Ws[Dv][128];
    const int nb = blockIdx.x;
    const int bh = blockIdx.y;
    const int b = bh >> 4, h = bh & 15;
    const int tid = threadIdx.x;
    const int tx = tid & 127;
    const int tz = tid >> 7;

    for (int idx = tid; idx < Dv * Dv; idx += 256)
        As[idx / Dv][idx % Dv] = attn[(size_t)bh * 2304 + idx];
    for (int idx = tid; idx < Dv * 128; idx += 256) {
        int i = idx >> 7, c = idx & 127;
        Ws[i][c] = Wp[(size_t)(h * Dv + i) * Ev + nb * 128 + c];
    }
    __syncthreads();

    float acc[24];
    #pragma unroll
    for (int j = 0; j < 24; j++) acc[j] = 0.f;
    #pragma unroll 4
    for (int i = 0; i < Dv; i++) {
        float a = Ws[i][tx];
        #pragma unroll
        for (int j = 0; j < 24; j++)
            acc[j] = fmaf(As[i][tz * 24 + j], a, acc[j]);
    }

    int n = nb * 128 + tx;
    uint32_t* ob = Pt2 + (size_t)b * Ev * LDKU + (size_t)n * LDKU;
    #pragma unroll
    for (int t = 0; t < 12; t++) {
        uint32_t h0, l0, h1, l1;
        split2(acc[2 * t], h0, l0);
        split2(acc[2 * t + 1], h1, l1);
        uint32_t* o = ob + 3 * (h * 24 + tz * 12 + t);
        o[0] = h0 | (h0 << 16);   // A layout
        o[1] = l0 | (h1 << 16);
        o[2] = h1 | (l1 << 16);
    }
}

// ---------------------------------------------------------------------------
// Launch
// ---------------------------------------------------------------------------
extern "C" void kernel_launch(void* const* d_in, const int* in_sizes, int n_in,
                              void* d_out, int out_size)
{
    const float* x      = (const float*)d_in[0];
    const float* W_qkv  = (const float*)d_in[1];
    const float* W_proj = (const float*)d_in[2];
    const float* b_proj = (const float*)d_in[3];
    const float* temp   = (const float*)d_in[4];
    float* outp = (float*)d_out;

    uint32_t *x2, *xtH, *xtL, *Cp, *wt1, *wv2, *Pt2, *wbT;
    float *R1, *R2, *V2, *gram;
    cudaGetSymbolAddress((void**)&x2, g_x2);
    cudaGetSymbolAddress((void**)&xtH, g_xtH);
    cudaGetSymbolAddress((void**)&xtL, g_xtL);
    cudaGetSymbolAddress((void**)&Cp, g_Cp);
    cudaGetSymbolAddress((void**)&wt1, g_wt1);
    cudaGetSymbolAddress((void**)&wv2, g_wv2);
    cudaGetSymbolAddress((void**)&Pt2, g_Pt2);
    cudaGetSymbolAddress((void**)&wbT, g_wbT);
    cudaGetSymbolAddress((void**)&R1, g_R1);
    cudaGetSymbolAddress((void**)&R2, g_R2);
    cudaGetSymbolAddress((void**)&V2, g_V2);
    cudaGetSymbolAddress((void**)&gram, g_gram);

    cudaFuncSetAttribute(gemm_mma, cudaFuncAttributeMaxDynamicSharedMemorySize,
                         GEMM_SMEM);

    // packing
    {
        dim3 grid(12, 49, 16);
        pack_x<<<grid, 256>>>(x, x2, xtH, xtL);
    }
    pack_wt<<<(1536 * 384) / 256, 256>>>(W_qkv, wt1, 1536, 2304);
    pack_wv<<<(Ev * 384) / 256, 256>>>(W_qkv, wv2);

    // merged: R1 = H^T H (triangular, 21 tiles) + R2 = H^T L (36 tiles)
    {
        dim3 grid(21 + 36, 16);
        gemm_mma<<<grid, 256, GEMM_SMEM>>>(
            (const char*)xtH, (const char*)xtH, R1, nullptr, Ev, 6,
            (size_t)Ev * LDH, (size_t)Ev * LDH, (size_t)Ev * Ev,
            1 << 30, LDH, 49, 21, (const char*)xtL, R2, 0);
    }
    // C = R1 + R2 + R2^T, packed A-triplet
    {
        dim3 grid(1152, 16);
        pack_ct<<<grid, 256>>>(R1, R2, Cp);
    }
    // V2 = C @ [Wq|Wk]
    {
        dim3 grid(6 * 12, 16);
        gemm_mma<<<grid, 256, GEMM_SMEM>>>(
            (const char*)Cp, (const char*)wt1, V2, nullptr, 1536, 12,
            (size_t)Ev * LDK, 0, (size_t)Ev * 1536, 1 << 30, LDK, 36, 0,
            nullptr, nullptr, 0);
    }
    // G + norms + softmax (fused)
    k_gs<<<256, 256>>>(W_qkv, V2, temp, gram);

    // fold P_b^T (A layout)
    {
        dim3 grid(6, 256);
        k_fold<<<grid, 256>>>(gram, W_proj, Pt2);
    }
    // WbT[n,e] = sum_m Pt[n,m] Wv[e,m] — packed triplet epilogue, no fp32 pass
    {
        dim3 grid(36, 16);
        gemm_mma<<<grid, 256, GEMM_SMEM>>>(
            (const char*)Pt2, (const char*)wv2, (float*)wbT, nullptr, Ev, 6,
            (size_t)Ev * LDKU * 4, 0, (size_t)Ev * LDKU, 1 << 30, LDK, 36, 0,
            nullptr, nullptr, 1);
    }
    // final: out_b = X_b @ W_b + b_proj
    {
        dim3 grid(25 * 6, 16);
        gemm_mma<<<grid, 256, GEMM_SMEM>>>(
            (const char*)x2, (const char*)wbT, outp, b_proj, Ev, 6,
            (size_t)Sv * LDK, (size_t)Ev * LDKU * 4, (size_t)Sv * Ev,
            Sv, LDK, 36, 0, nullptr, nullptr, 0);
    }
}